// round 6
// baseline (speedup 1.0000x reference)
#include <cuda_runtime.h>
#include <math.h>

#define DM 1024
#define DF 4096
#define NE 8
#define NSLOT 16
#define BB 4
#define TT 4096
#define BT (BB*TT)
#define NCHUNK 64           // 64-token chunks per batch
#define CT 64               // tokens per chunk
#define KSPLIT 16           // k5: d-chunks of 64
#define FSPLIT 64           // k5b: f-chunks of 64

// ---------------- scratch (device globals, no allocation) ----------------
__device__ float g_logits[BT * NSLOT];                 // 1 MB
__device__ float g_csum_p[BB * NCHUNK * NSLOT];
__device__ float g_psum[BB * NCHUNK * NSLOT * DM];     // 16 MB  [b*64+tc][n][d]
__device__ float g_si[NE * DM * 8];                    // 256 KB [e][d][m]
__device__ float g_s1[64 * 4];
__device__ float g_s2[64 * 4];
__device__ float g_mean[NE * 8];
__device__ float g_rstd[NE * 8];
__device__ float g_pu[KSPLIT * NE * DF * 8];           // 16 MB  [ks][e][f][m]
__device__ float g_pso[FSPLIT * NE * DM * 8];          // 16 MB  [fs][e][d][m]
__device__ float g_so[BB * NSLOT * DM];                // 256 KB [b][n][d]

// ---------------- K13: fused logits + dispatch-softmax weighted sums ----------------
__global__ __launch_bounds__(256) void k13_fused(const float* __restrict__ x,
                                                 const float* __restrict__ se) {
    __shared__ float xs[CT * 65];
    __shared__ float ss[NSLOT * 64];
    __shared__ float ls[CT * NSLOT];
    __shared__ float ws[CT * NSLOT];
    int tid = threadIdx.x;
    int tc = blockIdx.x, b = blockIdx.y;
    int t0 = tc * CT;
    const float* xb = x + (size_t)(b * TT + t0) * DM;
    int tw = tid & 31, np = tid >> 5;
    float a00 = 0.f, a01 = 0.f, a10 = 0.f, a11 = 0.f;

    for (int dt = 0; dt < DM; dt += 64) {
        {
            int n = tid >> 4, dq = tid & 15;
            *(float4*)(ss + n * 64 + dq * 4) =
                *(const float4*)(se + (size_t)n * DM + dt + dq * 4);
        }
#pragma unroll
        for (int r = 0; r < 4; r++) {
            int idx = tid + 256 * r;
            int t = idx >> 4, dq = idx & 15;
            float4 v = *(const float4*)(xb + (size_t)t * DM + dt + dq * 4);
            float* p = xs + t * 65 + dq * 4;
            p[0] = v.x; p[1] = v.y; p[2] = v.z; p[3] = v.w;
        }
        __syncthreads();
#pragma unroll 8
        for (int d = 0; d < 64; d++) {
            float s0 = ss[(2 * np) * 64 + d];
            float s1 = ss[(2 * np + 1) * 64 + d];
            float x0 = xs[tw * 65 + d];
            float x1 = xs[(tw + 32) * 65 + d];
            a00 += x0 * s0; a01 += x0 * s1;
            a10 += x1 * s0; a11 += x1 * s1;
        }
        __syncthreads();
    }
    ls[tw * 16 + 2 * np]            = a00 * 0.03125f;
    ls[tw * 16 + 2 * np + 1]        = a01 * 0.03125f;
    ls[(tw + 32) * 16 + 2 * np]     = a10 * 0.03125f;
    ls[(tw + 32) * 16 + 2 * np + 1] = a11 * 0.03125f;
    __syncthreads();

    float* lg = g_logits + (size_t)(b * TT + t0) * NSLOT;
#pragma unroll
    for (int r = 0; r < 4; r++) {
        int idx = tid + 256 * r;
        float l = ls[idx];
        lg[idx] = l;
        ws[idx] = expf(l);
    }
    __syncthreads();

    if (tid < 16) {
        float s = 0.f;
        for (int t = 0; t < CT; t++) s += ws[t * 16 + tid];
        g_csum_p[(b * NCHUNK + tc) * 16 + tid] = s;
    }

    float4 acc[16];
#pragma unroll
    for (int n = 0; n < 16; n++) acc[n] = make_float4(0.f, 0.f, 0.f, 0.f);
    const float* xp = xb + tid * 4;
    for (int t = 0; t < CT; t++) {
        float4 xv = *(const float4*)(xp + (size_t)t * DM);
#pragma unroll
        for (int n = 0; n < 16; n++) {
            float w = ws[t * 16 + n];
            acc[n].x += w * xv.x; acc[n].y += w * xv.y;
            acc[n].z += w * xv.z; acc[n].w += w * xv.w;
        }
    }
    float* op = g_psum + (size_t)(b * NCHUNK + tc) * 16 * DM + tid * 4;
#pragma unroll
    for (int n = 0; n < 16; n++)
        *(float4*)(op + (size_t)n * DM) = acc[n];
}

// ---------------- K4a: reduce partials, normalize, transpose, partial LN stats ----
__global__ __launch_bounds__(256) void k4a_reduce() {
    __shared__ float red[256];
    int bn = blockIdx.x, dc = blockIdx.y;
    int b = bn >> 4, n = bn & 15;
    int tid = threadIdx.x;
    if (tid < NCHUNK) red[tid] = g_csum_p[(b * NCHUNK + tid) * 16 + n];
    __syncthreads();
    if (tid == 0) {
        float s = 0.f;
        for (int i = 0; i < NCHUNK; i++) s += red[i];
        red[0] = 1.0f / s;
    }
    __syncthreads();
    float inv = red[0];
    __syncthreads();

    int d = dc * 256 + tid;
    const float* pp = g_psum + ((size_t)(b * NCHUNK) * 16 + n) * DM + d;
    float v = 0.f;
#pragma unroll 4
    for (int t = 0; t < NCHUNK; t++) v += pp[(size_t)t * 16 * DM];
    v *= inv;
    int e = n >> 1, sl = n & 1, m = (b << 1) | sl;
    g_si[((size_t)e * DM + d) * 8 + m] = v;

    red[tid] = v; __syncthreads();
    for (int s = 128; s > 0; s >>= 1) {
        if (tid < s) red[tid] += red[tid + s];
        __syncthreads();
    }
    float s1 = red[0]; __syncthreads();
    red[tid] = v * v; __syncthreads();
    for (int s = 128; s > 0; s >>= 1) {
        if (tid < s) red[tid] += red[tid + s];
        __syncthreads();
    }
    if (tid == 0) { g_s1[bn * 4 + dc] = s1; g_s2[bn * 4 + dc] = red[0]; }
}

// ---------------- K4b: finalize LN stats ----------------
__global__ void k4b_stats() {
    int bn = threadIdx.x;
    if (bn < 64) {
        float s1 = 0.f, s2 = 0.f;
#pragma unroll
        for (int q = 0; q < 4; q++) { s1 += g_s1[bn * 4 + q]; s2 += g_s2[bn * 4 + q]; }
        float mean = s1 * (1.0f / DM);
        float var = fmaxf(s2 * (1.0f / DM) - mean * mean, 0.f);
        int b = bn >> 4, n = bn & 15;
        int e = n >> 1, m = (b << 1) | (n & 1);
        g_mean[e * 8 + m] = mean;
        g_rstd[e * 8 + m] = rsqrtf(var + 1e-5f);
    }
}

// ---------------- K5: GEMM1 pu[ks][e][f][m] = LN(si) . W1 ----------------
// grid (fc=8, e=8, ks=16) = 1024 blocks, block 256.
// tid = mh*128 + fslot: thread owns 4 f cols x 4 m rows (m-half mh).
// Both m-halves read the same W float4 -> L1 broadcast, W streamed once.
__global__ __launch_bounds__(256) void k5_gemm1(const float* __restrict__ W1,
                                                const float* __restrict__ gamma,
                                                const float* __restrict__ beta) {
    __shared__ float hs[64 * 8];
    int tid = threadIdx.x;
    int fc = blockIdx.x, e = blockIdx.y, ks = blockIdx.z;
    if (tid < 128) {   // stage 64 d x 8 m with LN applied
        int d = ks * 64 + (tid >> 1);
        int mb = (tid & 1) * 4;
        float4 v = *(const float4*)(g_si + ((size_t)e * DM + d) * 8 + mb);
        float4 mu = *(const float4*)(g_mean + e * 8 + mb);
        float4 rs = *(const float4*)(g_rstd + e * 8 + mb);
        float ga = gamma[d], be = beta[d];
        v.x = (v.x - mu.x) * rs.x * ga + be;
        v.y = (v.y - mu.y) * rs.y * ga + be;
        v.z = (v.z - mu.z) * rs.z * ga + be;
        v.w = (v.w - mu.w) * rs.w * ga + be;
        *(float4*)(hs + tid * 4) = v;
    }
    __syncthreads();
    int mh = tid >> 7;            // m-half 0/1
    int fsl = tid & 127;
    int f0 = fc * 512 + fsl * 4;
    const float* wp = W1 + ((size_t)e * DM + ks * 64) * DF + f0;
    float acc[4][4];
#pragma unroll
    for (int i = 0; i < 4; i++)
#pragma unroll
        for (int j = 0; j < 4; j++) acc[i][j] = 0.f;
#pragma unroll 4
    for (int dd = 0; dd < 64; dd++) {
        float4 w = *(const float4*)(wp + (size_t)dd * DF);
        float4 h = *(const float4*)(hs + dd * 8 + mh * 4);
        acc[0][0] += h.x * w.x; acc[0][1] += h.x * w.y; acc[0][2] += h.x * w.z; acc[0][3] += h.x * w.w;
        acc[1][0] += h.y * w.x; acc[1][1] += h.y * w.y; acc[1][2] += h.y * w.z; acc[1][3] += h.y * w.w;
        acc[2][0] += h.z * w.x; acc[2][1] += h.z * w.y; acc[2][2] += h.z * w.z; acc[2][3] += h.z * w.w;
        acc[3][0] += h.w * w.x; acc[3][1] += h.w * w.y; acc[3][2] += h.w * w.z; acc[3][3] += h.w * w.w;
    }
    float* op = g_pu + ((size_t)(ks * NE + e) * DF + f0) * 8 + mh * 4;
#pragma unroll
    for (int j = 0; j < 4; j++)
        *(float4*)(op + j * 8) = make_float4(acc[0][j], acc[1][j], acc[2][j], acc[3][j]);
}

__device__ __forceinline__ float gelu_exact(float v) {
    return 0.5f * v * (1.0f + erff(v * 0.70710678118654752f));
}

// ---------------- K5b: GEMM2 pso[fs][e][d][m] = gelu(sum pu) . W2 ----------------
// grid (dc=2, e=8, fs=64) = 1024 blocks, block 256; same 4m x 4d thread tile.
__global__ __launch_bounds__(256) void k5b_gemm2(const float* __restrict__ W2) {
    __shared__ float us[64 * 8];
    int tid = threadIdx.x;
    int dc = blockIdx.x, e = blockIdx.y, fs = blockIdx.z;
    if (tid < 128) {   // stage u = gelu(sum of 16 k-split partials)
        int f = fs * 64 + (tid >> 1);
        int mb = (tid & 1) * 4;
        const float* pp = g_pu + ((size_t)e * DF + f) * 8 + mb;
        float4 s = *(const float4*)pp;
#pragma unroll
        for (int kq = 1; kq < KSPLIT; kq++) {
            float4 v = *(const float4*)(pp + (size_t)kq * NE * DF * 8);
            s.x += v.x; s.y += v.y; s.z += v.z; s.w += v.w;
        }
        float4 g;
        g.x = gelu_exact(s.x); g.y = gelu_exact(s.y);
        g.z = gelu_exact(s.z); g.w = gelu_exact(s.w);
        *(float4*)(us + tid * 4) = g;
    }
    __syncthreads();
    int mh = tid >> 7;
    int dsl = tid & 127;
    int d0 = dc * 512 + dsl * 4;
    const float* wp = W2 + ((size_t)e * DF + fs * 64) * DM + d0;
    float acc[4][4];
#pragma unroll
    for (int i = 0; i < 4; i++)
#pragma unroll
        for (int j = 0; j < 4; j++) acc[i][j] = 0.f;
#pragma unroll 4
    for (int ff = 0; ff < 64; ff++) {
        float4 w = *(const float4*)(wp + (size_t)ff * DM);
        float4 u = *(const float4*)(us + ff * 8 + mh * 4);
        acc[0][0] += u.x * w.x; acc[0][1] += u.x * w.y; acc[0][2] += u.x * w.z; acc[0][3] += u.x * w.w;
        acc[1][0] += u.y * w.x; acc[1][1] += u.y * w.y; acc[1][2] += u.y * w.z; acc[1][3] += u.y * w.w;
        acc[2][0] += u.z * w.x; acc[2][1] += u.z * w.y; acc[2][2] += u.z * w.z; acc[2][3] += u.z * w.w;
        acc[3][0] += u.w * w.x; acc[3][1] += u.w * w.y; acc[3][2] += u.w * w.z; acc[3][3] += u.w * w.w;
    }
    float* op = g_pso + ((size_t)(fs * NE + e) * DM + d0) * 8 + mh * 4;
#pragma unroll
    for (int j = 0; j < 4; j++)
        *(float4*)(op + j * 8) = make_float4(acc[0][j], acc[1][j], acc[2][j], acc[3][j]);
}

// ---------------- K5c: reduce 64 f-split partials -> slot_out[b][n][d] ----------------
__global__ __launch_bounds__(128) void k5c_reduce() {
    int idx = blockIdx.x * 128 + threadIdx.x;  // 0..16383
    int e = idx >> 11;
    int rest = idx & 2047;
    int d = rest >> 1, mh = rest & 1;
    const float* pp = g_pso + ((size_t)e * DM + d) * 8 + mh * 4;
    float4 a = *(const float4*)pp;
#pragma unroll 8
    for (int fs = 1; fs < FSPLIT; fs++) {
        float4 v = *(const float4*)(pp + (size_t)fs * NE * DM * 8);
        a.x += v.x; a.y += v.y; a.z += v.z; a.w += v.w;
    }
    int m0 = mh * 4;
    float vals[4] = {a.x, a.y, a.z, a.w};
#pragma unroll
    for (int j = 0; j < 4; j++) {
        int m = m0 + j;
        int b = m >> 1, sl = m & 1;
        g_so[(size_t)(b * 16 + e * 2 + sl) * DM + d] = vals[j];
    }
}

// ---------------- K6: combine = softmax_n(logits) @ slot_out ----------------
__global__ __launch_bounds__(256) void k6_combine(float* __restrict__ out) {
    __shared__ float cs[64 * 16];
    int tc = blockIdx.x, b = blockIdx.y;
    int tid = threadIdx.x;
    int t0 = tc * 64;
    if (tid < 64) {
        const float* lp = g_logits + (size_t)(b * TT + t0 + tid) * NSLOT;
        float l[16];
#pragma unroll
        for (int n = 0; n < 16; n++) l[n] = lp[n];
        float m = l[0];
#pragma unroll
        for (int n = 1; n < 16; n++) m = fmaxf(m, l[n]);
        float sum = 0.f;
#pragma unroll
        for (int n = 0; n < 16; n++) { l[n] = expf(l[n] - m); sum += l[n]; }
        float inv = 1.0f / sum;
#pragma unroll
        for (int n = 0; n < 16; n++) cs[tid * 16 + n] = l[n] * inv;
    }
    __syncthreads();
    float4 sv[16];
    const float* sp = g_so + (size_t)b * 16 * DM + tid * 4;
#pragma unroll
    for (int n = 0; n < 16; n++) sv[n] = *(const float4*)(sp + (size_t)n * DM);
    float* op = out + (size_t)(b * TT + t0) * DM + tid * 4;
    for (int t = 0; t < 64; t++) {
        float4 acc = make_float4(0.f, 0.f, 0.f, 0.f);
#pragma unroll
        for (int n = 0; n < 16; n++) {
            float c = cs[t * 16 + n];
            acc.x += c * sv[n].x; acc.y += c * sv[n].y;
            acc.z += c * sv[n].z; acc.w += c * sv[n].w;
        }
        *(float4*)(op + (size_t)t * DM) = acc;
    }
}

// ---------------- launch ----------------
extern "C" void kernel_launch(void* const* d_in, const int* in_sizes, int n_in,
                              void* d_out, int out_size) {
    const float* x     = (const float*)d_in[0];
    const float* se    = (const float*)d_in[1];
    const float* W1    = (const float*)d_in[2];
    const float* W2    = (const float*)d_in[3];
    const float* gamma = (const float*)d_in[4];
    const float* beta  = (const float*)d_in[5];
    float* out = (float*)d_out;

    { dim3 g(NCHUNK, BB);        k13_fused<<<g, 256>>>(x, se); }
    { dim3 g(64, 4);             k4a_reduce<<<g, 256>>>(); }
    k4b_stats<<<1, 64>>>();
    { dim3 g(8, NE, KSPLIT);     k5_gemm1<<<g, 256>>>(W1, gamma, beta); }
    { dim3 g(2, NE, FSPLIT);     k5b_gemm2<<<g, 256>>>(W2); }
    k5c_reduce<<<128, 128>>>();
    { dim3 g(64, BB);            k6_combine<<<g, 256>>>(out); }
}

// round 11
// speedup vs baseline: 1.0526x; 1.0526x over previous
#include <cuda_runtime.h>
#include <math.h>

#define DM 1024
#define DF 4096
#define NE 8
#define NSLOT 16
#define BB 4
#define TT 4096
#define BT (BB*TT)
#define NCHUNK 64           // 64-token chunks per batch
#define CT 64               // tokens per chunk
#define KSPLIT 8            // k5: d-chunks of 128
#define FSPLIT 32           // k5b: f-chunks of 128

// ---------------- scratch (device globals, no allocation) ----------------
__device__ float g_logits[BT * NSLOT];                 // 1 MB
__device__ float g_csum_p[BB * NCHUNK * NSLOT];
__device__ float g_psum[BB * NCHUNK * NSLOT * DM];     // 16 MB  [b*64+tc][n][d]
__device__ float g_si[NE * DM * 8];                    // 256 KB [e][d][m]
__device__ float g_s1[64 * 4];
__device__ float g_s2[64 * 4];
__device__ float g_mean[NE * 8];
__device__ float g_rstd[NE * 8];
__device__ float g_pu[KSPLIT * NE * DF * 8];           // 8 MB   [ks][e][f][m]
__device__ float g_pso[FSPLIT * NE * DM * 8];          // 8 MB   [fs][e][d][m]
__device__ float g_so[BB * NSLOT * DM];                // 256 KB [b][n][d]

// ---------------- K13: fused logits + dispatch-softmax weighted sums ----------------
__global__ __launch_bounds__(256) void k13_fused(const float* __restrict__ x,
                                                 const float* __restrict__ se) {
    __shared__ float xs[CT * 65];
    __shared__ float ss[NSLOT * 64];
    __shared__ float ls[CT * NSLOT];
    __shared__ float ws[CT * NSLOT];
    int tid = threadIdx.x;
    int tc = blockIdx.x, b = blockIdx.y;
    int t0 = tc * CT;
    const float* xb = x + (size_t)(b * TT + t0) * DM;
    int tw = tid & 31, np = tid >> 5;
    float a00 = 0.f, a01 = 0.f, a10 = 0.f, a11 = 0.f;

    for (int dt = 0; dt < DM; dt += 64) {
        {
            int n = tid >> 4, dq = tid & 15;
            *(float4*)(ss + n * 64 + dq * 4) =
                *(const float4*)(se + (size_t)n * DM + dt + dq * 4);
        }
#pragma unroll
        for (int r = 0; r < 4; r++) {
            int idx = tid + 256 * r;
            int t = idx >> 4, dq = idx & 15;
            float4 v = *(const float4*)(xb + (size_t)t * DM + dt + dq * 4);
            float* p = xs + t * 65 + dq * 4;
            p[0] = v.x; p[1] = v.y; p[2] = v.z; p[3] = v.w;
        }
        __syncthreads();
#pragma unroll 8
        for (int d = 0; d < 64; d++) {
            float s0 = ss[(2 * np) * 64 + d];
            float s1 = ss[(2 * np + 1) * 64 + d];
            float x0 = xs[tw * 65 + d];
            float x1 = xs[(tw + 32) * 65 + d];
            a00 += x0 * s0; a01 += x0 * s1;
            a10 += x1 * s0; a11 += x1 * s1;
        }
        __syncthreads();
    }
    ls[tw * 16 + 2 * np]            = a00 * 0.03125f;
    ls[tw * 16 + 2 * np + 1]        = a01 * 0.03125f;
    ls[(tw + 32) * 16 + 2 * np]     = a10 * 0.03125f;
    ls[(tw + 32) * 16 + 2 * np + 1] = a11 * 0.03125f;
    __syncthreads();

    float* lg = g_logits + (size_t)(b * TT + t0) * NSLOT;
#pragma unroll
    for (int r = 0; r < 4; r++) {
        int idx = tid + 256 * r;
        float l = ls[idx];
        lg[idx] = l;
        ws[idx] = expf(l);
    }
    __syncthreads();

    if (tid < 16) {
        float s = 0.f;
        for (int t = 0; t < CT; t++) s += ws[t * 16 + tid];
        g_csum_p[(b * NCHUNK + tc) * 16 + tid] = s;
    }

    float4 acc[16];
#pragma unroll
    for (int n = 0; n < 16; n++) acc[n] = make_float4(0.f, 0.f, 0.f, 0.f);
    const float* xp = xb + tid * 4;
    for (int t = 0; t < CT; t++) {
        float4 xv = *(const float4*)(xp + (size_t)t * DM);
#pragma unroll
        for (int n = 0; n < 16; n++) {
            float w = ws[t * 16 + n];
            acc[n].x += w * xv.x; acc[n].y += w * xv.y;
            acc[n].z += w * xv.z; acc[n].w += w * xv.w;
        }
    }
    float* op = g_psum + (size_t)(b * NCHUNK + tc) * 16 * DM + tid * 4;
#pragma unroll
    for (int n = 0; n < 16; n++)
        *(float4*)(op + (size_t)n * DM) = acc[n];
}

// ---------------- K4a: reduce partials, normalize, transpose, partial LN stats ----
__global__ __launch_bounds__(256) void k4a_reduce() {
    __shared__ float red[256];
    int bn = blockIdx.x, dc = blockIdx.y;
    int b = bn >> 4, n = bn & 15;
    int tid = threadIdx.x;
    if (tid < NCHUNK) red[tid] = g_csum_p[(b * NCHUNK + tid) * 16 + n];
    __syncthreads();
    if (tid == 0) {
        float s = 0.f;
        for (int i = 0; i < NCHUNK; i++) s += red[i];
        red[0] = 1.0f / s;
    }
    __syncthreads();
    float inv = red[0];
    __syncthreads();

    int d = dc * 256 + tid;
    const float* pp = g_psum + ((size_t)(b * NCHUNK) * 16 + n) * DM + d;
    float v = 0.f;
#pragma unroll 4
    for (int t = 0; t < NCHUNK; t++) v += pp[(size_t)t * 16 * DM];
    v *= inv;
    int e = n >> 1, sl = n & 1, m = (b << 1) | sl;
    g_si[((size_t)e * DM + d) * 8 + m] = v;

    red[tid] = v; __syncthreads();
    for (int s = 128; s > 0; s >>= 1) {
        if (tid < s) red[tid] += red[tid + s];
        __syncthreads();
    }
    float s1 = red[0]; __syncthreads();
    red[tid] = v * v; __syncthreads();
    for (int s = 128; s > 0; s >>= 1) {
        if (tid < s) red[tid] += red[tid + s];
        __syncthreads();
    }
    if (tid == 0) { g_s1[bn * 4 + dc] = s1; g_s2[bn * 4 + dc] = red[0]; }
}

// ---------------- K4b: finalize LN stats ----------------
__global__ void k4b_stats() {
    int bn = threadIdx.x;
    if (bn < 64) {
        float s1 = 0.f, s2 = 0.f;
#pragma unroll
        for (int q = 0; q < 4; q++) { s1 += g_s1[bn * 4 + q]; s2 += g_s2[bn * 4 + q]; }
        float mean = s1 * (1.0f / DM);
        float var = fmaxf(s2 * (1.0f / DM) - mean * mean, 0.f);
        int b = bn >> 4, n = bn & 15;
        int e = n >> 1, m = (b << 1) | (n & 1);
        g_mean[e * 8 + m] = mean;
        g_rstd[e * 8 + m] = rsqrtf(var + 1e-5f);
    }
}

// ---------------- K5: GEMM1 pu[ks][e][f][m] = LN(si) . W1 ----------------
// grid (fc=8, e=8, ks=8) = 512 blocks (single resident wave), block 256.
// Each block: 128-d slab x 512-f stripe = 256 KB of W1.
// tid = mh*128 + fslot: thread owns 4 f cols x 4 m rows (m-half mh).
__global__ __launch_bounds__(256) void k5_gemm1(const float* __restrict__ W1,
                                                const float* __restrict__ gamma,
                                                const float* __restrict__ beta) {
    __shared__ float hs[128 * 8];
    int tid = threadIdx.x;
    int fc = blockIdx.x, e = blockIdx.y, ks = blockIdx.z;
    {   // stage 128 d x 8 m with LN applied (all 256 threads)
        int d = ks * 128 + (tid >> 1);
        int mb = (tid & 1) * 4;
        float4 v = *(const float4*)(g_si + ((size_t)e * DM + d) * 8 + mb);
        float4 mu = *(const float4*)(g_mean + e * 8 + mb);
        float4 rs = *(const float4*)(g_rstd + e * 8 + mb);
        float ga = gamma[d], be = beta[d];
        v.x = (v.x - mu.x) * rs.x * ga + be;
        v.y = (v.y - mu.y) * rs.y * ga + be;
        v.z = (v.z - mu.z) * rs.z * ga + be;
        v.w = (v.w - mu.w) * rs.w * ga + be;
        *(float4*)(hs + tid * 4) = v;
    }
    __syncthreads();
    int mh = tid >> 7;            // m-half 0/1
    int fsl = tid & 127;
    int f0 = fc * 512 + fsl * 4;
    const float* wp = W1 + ((size_t)e * DM + ks * 128) * DF + f0;
    float acc[4][4];
#pragma unroll
    for (int i = 0; i < 4; i++)
#pragma unroll
        for (int j = 0; j < 4; j++) acc[i][j] = 0.f;
#pragma unroll 8
    for (int dd = 0; dd < 128; dd++) {
        float4 w = *(const float4*)(wp + (size_t)dd * DF);
        float4 h = *(const float4*)(hs + dd * 8 + mh * 4);
        acc[0][0] += h.x * w.x; acc[0][1] += h.x * w.y; acc[0][2] += h.x * w.z; acc[0][3] += h.x * w.w;
        acc[1][0] += h.y * w.x; acc[1][1] += h.y * w.y; acc[1][2] += h.y * w.z; acc[1][3] += h.y * w.w;
        acc[2][0] += h.z * w.x; acc[2][1] += h.z * w.y; acc[2][2] += h.z * w.z; acc[2][3] += h.z * w.w;
        acc[3][0] += h.w * w.x; acc[3][1] += h.w * w.y; acc[3][2] += h.w * w.z; acc[3][3] += h.w * w.w;
    }
    float* op = g_pu + ((size_t)(ks * NE + e) * DF + f0) * 8 + mh * 4;
#pragma unroll
    for (int j = 0; j < 4; j++)
        *(float4*)(op + j * 8) = make_float4(acc[0][j], acc[1][j], acc[2][j], acc[3][j]);
}

__device__ __forceinline__ float gelu_exact(float v) {
    return 0.5f * v * (1.0f + erff(v * 0.70710678118654752f));
}

// ---------------- K5b: GEMM2 pso[fs][e][d][m] = gelu(sum pu) . W2 ----------------
// grid (dc=2, e=8, fs=32) = 512 blocks; each block: 128-f slab x 512-d stripe.
__global__ __launch_bounds__(256) void k5b_gemm2(const float* __restrict__ W2) {
    __shared__ float us[128 * 8];
    int tid = threadIdx.x;
    int dc = blockIdx.x, e = blockIdx.y, fs = blockIdx.z;
    {   // stage u = gelu(sum of 8 k-split partials), all 256 threads
        int f = fs * 128 + (tid >> 1);
        int mb = (tid & 1) * 4;
        const float* pp = g_pu + ((size_t)e * DF + f) * 8 + mb;
        float4 s = *(const float4*)pp;
#pragma unroll
        for (int kq = 1; kq < KSPLIT; kq++) {
            float4 v = *(const float4*)(pp + (size_t)kq * NE * DF * 8);
            s.x += v.x; s.y += v.y; s.z += v.z; s.w += v.w;
        }
        float4 g;
        g.x = gelu_exact(s.x); g.y = gelu_exact(s.y);
        g.z = gelu_exact(s.z); g.w = gelu_exact(s.w);
        *(float4*)(us + tid * 4) = g;
    }
    __syncthreads();
    int mh = tid >> 7;
    int dsl = tid & 127;
    int d0 = dc * 512 + dsl * 4;
    const float* wp = W2 + ((size_t)e * DF + fs * 128) * DM + d0;
    float acc[4][4];
#pragma unroll
    for (int i = 0; i < 4; i++)
#pragma unroll
        for (int j = 0; j < 4; j++) acc[i][j] = 0.f;
#pragma unroll 8
    for (int ff = 0; ff < 128; ff++) {
        float4 w = *(const float4*)(wp + (size_t)ff * DM);
        float4 u = *(const float4*)(us + ff * 8 + mh * 4);
        acc[0][0] += u.x * w.x; acc[0][1] += u.x * w.y; acc[0][2] += u.x * w.z; acc[0][3] += u.x * w.w;
        acc[1][0] += u.y * w.x; acc[1][1] += u.y * w.y; acc[1][2] += u.y * w.z; acc[1][3] += u.y * w.w;
        acc[2][0] += u.z * w.x; acc[2][1] += u.z * w.y; acc[2][2] += u.z * w.z; acc[2][3] += u.z * w.w;
        acc[3][0] += u.w * w.x; acc[3][1] += u.w * w.y; acc[3][2] += u.w * w.z; acc[3][3] += u.w * w.w;
    }
    float* op = g_pso + ((size_t)(fs * NE + e) * DM + d0) * 8 + mh * 4;
#pragma unroll
    for (int j = 0; j < 4; j++)
        *(float4*)(op + j * 8) = make_float4(acc[0][j], acc[1][j], acc[2][j], acc[3][j]);
}

// ---------------- K5c: reduce 32 f-split partials -> slot_out[b][n][d] ----------------
__global__ __launch_bounds__(128) void k5c_reduce() {
    int idx = blockIdx.x * 128 + threadIdx.x;  // 0..16383
    int e = idx >> 11;
    int rest = idx & 2047;
    int d = rest >> 1, mh = rest & 1;
    const float* pp = g_pso + ((size_t)e * DM + d) * 8 + mh * 4;
    float4 a = *(const float4*)pp;
#pragma unroll 8
    for (int fs = 1; fs < FSPLIT; fs++) {
        float4 v = *(const float4*)(pp + (size_t)fs * NE * DM * 8);
        a.x += v.x; a.y += v.y; a.z += v.z; a.w += v.w;
    }
    int m0 = mh * 4;
    float vals[4] = {a.x, a.y, a.z, a.w};
#pragma unroll
    for (int j = 0; j < 4; j++) {
        int m = m0 + j;
        int b = m >> 1, sl = m & 1;
        g_so[(size_t)(b * 16 + e * 2 + sl) * DM + d] = vals[j];
    }
}

// ---------------- K6: combine = softmax_n(logits) @ slot_out ----------------
__global__ __launch_bounds__(256) void k6_combine(float* __restrict__ out) {
    __shared__ float cs[64 * 16];
    int tc = blockIdx.x, b = blockIdx.y;
    int tid = threadIdx.x;
    int t0 = tc * 64;
    if (tid < 64) {
        const float* lp = g_logits + (size_t)(b * TT + t0 + tid) * NSLOT;
        float l[16];
#pragma unroll
        for (int n = 0; n < 16; n++) l[n] = lp[n];
        float m = l[0];
#pragma unroll
        for (int n = 1; n < 16; n++) m = fmaxf(m, l[n]);
        float sum = 0.f;
#pragma unroll
        for (int n = 0; n < 16; n++) { l[n] = expf(l[n] - m); sum += l[n]; }
        float inv = 1.0f / sum;
#pragma unroll
        for (int n = 0; n < 16; n++) cs[tid * 16 + n] = l[n] * inv;
    }
    __syncthreads();
    float4 sv[16];
    const float* sp = g_so + (size_t)b * 16 * DM + tid * 4;
#pragma unroll
    for (int n = 0; n < 16; n++) sv[n] = *(const float4*)(sp + (size_t)n * DM);
    float* op = out + (size_t)(b * TT + t0) * DM + tid * 4;
    for (int t = 0; t < 64; t++) {
        float4 acc = make_float4(0.f, 0.f, 0.f, 0.f);
#pragma unroll
        for (int n = 0; n < 16; n++) {
            float c = cs[t * 16 + n];
            acc.x += c * sv[n].x; acc.y += c * sv[n].y;
            acc.z += c * sv[n].z; acc.w += c * sv[n].w;
        }
        *(float4*)(op + (size_t)t * DM) = acc;
    }
}

// ---------------- launch ----------------
extern "C" void kernel_launch(void* const* d_in, const int* in_sizes, int n_in,
                              void* d_out, int out_size) {
    const float* x     = (const float*)d_in[0];
    const float* se    = (const float*)d_in[1];
    const float* W1    = (const float*)d_in[2];
    const float* W2    = (const float*)d_in[3];
    const float* gamma = (const float*)d_in[4];
    const float* beta  = (const float*)d_in[5];
    float* out = (float*)d_out;

    { dim3 g(NCHUNK, BB);        k13_fused<<<g, 256>>>(x, se); }
    { dim3 g(64, 4);             k4a_reduce<<<g, 256>>>(); }
    k4b_stats<<<1, 64>>>();
    { dim3 g(8, NE, KSPLIT);     k5_gemm1<<<g, 256>>>(W1, gamma, beta); }
    { dim3 g(2, NE, FSPLIT);     k5b_gemm2<<<g, 256>>>(W2); }
    k5c_reduce<<<128, 128>>>();
    { dim3 g(64, BB);            k6_combine<<<g, 256>>>(out); }
}

// round 12
// speedup vs baseline: 1.0760x; 1.0222x over previous
#include <cuda_runtime.h>
#include <math.h>

#define DM 1024
#define DF 4096
#define NE 8
#define NSLOT 16
#define BB 4
#define TT 4096
#define BT (BB*TT)
#define NCHUNK 64           // 64-token chunks per batch
#define CT 64               // tokens per chunk
#define KSPLIT 8            // k5: d-chunks of 128
#define FSPLIT 32           // k5b: f-chunks of 128

// ---------------- scratch (device globals, no allocation) ----------------
__device__ float g_logits[BT * NSLOT];                 // 1 MB
__device__ float g_csum_p[BB * NCHUNK * NSLOT];
__device__ float g_psum[BB * NCHUNK * NSLOT * DM];     // 16 MB  [b*64+tc][n][d]
__device__ float g_si[NE * DM * 8];                    // 256 KB [e][d][m]
__device__ float g_s1[64 * 4];
__device__ float g_s2[64 * 4];
__device__ float g_mean[NE * 8];
__device__ float g_rstd[NE * 8];
__device__ float g_pu[KSPLIT * NE * DF * 8];           // 8 MB   [ks][e][f][m]
__device__ float g_pso[FSPLIT * NE * DM * 8];          // 8 MB   [fs][e][d][m]
__device__ float g_so[BB * NSLOT * DM];                // 256 KB [b][n][d]

// ---------------- K13: fused logits + dispatch-softmax weighted sums ----------------
__global__ __launch_bounds__(256) void k13_fused(const float* __restrict__ x,
                                                 const float* __restrict__ se) {
    __shared__ float xs[CT * 65];
    __shared__ float ss[NSLOT * 64];
    __shared__ float ls[CT * NSLOT];
    __shared__ float ws[CT * NSLOT];
    int tid = threadIdx.x;
    int tc = blockIdx.x, b = blockIdx.y;
    int t0 = tc * CT;
    const float* xb = x + (size_t)(b * TT + t0) * DM;
    int tw = tid & 31, np = tid >> 5;
    float a00 = 0.f, a01 = 0.f, a10 = 0.f, a11 = 0.f;

    for (int dt = 0; dt < DM; dt += 64) {
        {
            int n = tid >> 4, dq = tid & 15;
            *(float4*)(ss + n * 64 + dq * 4) =
                *(const float4*)(se + (size_t)n * DM + dt + dq * 4);
        }
#pragma unroll
        for (int r = 0; r < 4; r++) {
            int idx = tid + 256 * r;
            int t = idx >> 4, dq = idx & 15;
            float4 v = *(const float4*)(xb + (size_t)t * DM + dt + dq * 4);
            float* p = xs + t * 65 + dq * 4;
            p[0] = v.x; p[1] = v.y; p[2] = v.z; p[3] = v.w;
        }
        __syncthreads();
#pragma unroll 8
        for (int d = 0; d < 64; d++) {
            float s0 = ss[(2 * np) * 64 + d];
            float s1 = ss[(2 * np + 1) * 64 + d];
            float x0 = xs[tw * 65 + d];
            float x1 = xs[(tw + 32) * 65 + d];
            a00 += x0 * s0; a01 += x0 * s1;
            a10 += x1 * s0; a11 += x1 * s1;
        }
        __syncthreads();
    }
    ls[tw * 16 + 2 * np]            = a00 * 0.03125f;
    ls[tw * 16 + 2 * np + 1]        = a01 * 0.03125f;
    ls[(tw + 32) * 16 + 2 * np]     = a10 * 0.03125f;
    ls[(tw + 32) * 16 + 2 * np + 1] = a11 * 0.03125f;
    __syncthreads();

    float* lg = g_logits + (size_t)(b * TT + t0) * NSLOT;
#pragma unroll
    for (int r = 0; r < 4; r++) {
        int idx = tid + 256 * r;
        float l = ls[idx];
        lg[idx] = l;
        ws[idx] = expf(l);
    }
    __syncthreads();

    if (tid < 16) {
        float s = 0.f;
        for (int t = 0; t < CT; t++) s += ws[t * 16 + tid];
        g_csum_p[(b * NCHUNK + tc) * 16 + tid] = s;
    }

    // Phase 2: weighted accumulation with depth-2 x prefetch (x is L2-hot)
    float4 acc[16];
#pragma unroll
    for (int n = 0; n < 16; n++) acc[n] = make_float4(0.f, 0.f, 0.f, 0.f);
    const float* xp = xb + tid * 4;
    float4 xnext = *(const float4*)xp;
#pragma unroll 1
    for (int t = 0; t < CT; t++) {
        float4 xv = xnext;
        if (t + 1 < CT) xnext = *(const float4*)(xp + (size_t)(t + 1) * DM);
#pragma unroll
        for (int n = 0; n < 16; n++) {
            float w = ws[t * 16 + n];
            acc[n].x += w * xv.x; acc[n].y += w * xv.y;
            acc[n].z += w * xv.z; acc[n].w += w * xv.w;
        }
    }
    float* op = g_psum + (size_t)(b * NCHUNK + tc) * 16 * DM + tid * 4;
#pragma unroll
    for (int n = 0; n < 16; n++)
        *(float4*)(op + (size_t)n * DM) = acc[n];
}

// ---------------- K4a: reduce partials, normalize, transpose, partial LN stats ----
__global__ __launch_bounds__(256) void k4a_reduce() {
    __shared__ float red[256];
    int bn = blockIdx.x, dc = blockIdx.y;
    int b = bn >> 4, n = bn & 15;
    int tid = threadIdx.x;
    if (tid < NCHUNK) red[tid] = g_csum_p[(b * NCHUNK + tid) * 16 + n];
    __syncthreads();
    if (tid == 0) {
        float s = 0.f;
        for (int i = 0; i < NCHUNK; i++) s += red[i];
        red[0] = 1.0f / s;
    }
    __syncthreads();
    float inv = red[0];
    __syncthreads();

    int d = dc * 256 + tid;
    const float* pp = g_psum + ((size_t)(b * NCHUNK) * 16 + n) * DM + d;
    float va = 0.f, vb = 0.f;
#pragma unroll 4
    for (int t = 0; t < NCHUNK; t += 2) {
        va += pp[(size_t)t * 16 * DM];
        vb += pp[(size_t)(t + 1) * 16 * DM];
    }
    float v = (va + vb) * inv;
    int e = n >> 1, sl = n & 1, m = (b << 1) | sl;
    g_si[((size_t)e * DM + d) * 8 + m] = v;

    red[tid] = v; __syncthreads();
    for (int s = 128; s > 0; s >>= 1) {
        if (tid < s) red[tid] += red[tid + s];
        __syncthreads();
    }
    float s1 = red[0]; __syncthreads();
    red[tid] = v * v; __syncthreads();
    for (int s = 128; s > 0; s >>= 1) {
        if (tid < s) red[tid] += red[tid + s];
        __syncthreads();
    }
    if (tid == 0) { g_s1[bn * 4 + dc] = s1; g_s2[bn * 4 + dc] = red[0]; }
}

// ---------------- K4b: finalize LN stats ----------------
__global__ void k4b_stats() {
    int bn = threadIdx.x;
    if (bn < 64) {
        float s1 = 0.f, s2 = 0.f;
#pragma unroll
        for (int q = 0; q < 4; q++) { s1 += g_s1[bn * 4 + q]; s2 += g_s2[bn * 4 + q]; }
        float mean = s1 * (1.0f / DM);
        float var = fmaxf(s2 * (1.0f / DM) - mean * mean, 0.f);
        int b = bn >> 4, n = bn & 15;
        int e = n >> 1, m = (b << 1) | (n & 1);
        g_mean[e * 8 + m] = mean;
        g_rstd[e * 8 + m] = rsqrtf(var + 1e-5f);
    }
}

// FMA micro-tile: 4 m-rows x 4 f-cols with one weight float4
#define TILE_FMA(ACC, H, W) \
    ACC[0][0] += H.x * W.x; ACC[0][1] += H.x * W.y; ACC[0][2] += H.x * W.z; ACC[0][3] += H.x * W.w; \
    ACC[1][0] += H.y * W.x; ACC[1][1] += H.y * W.y; ACC[1][2] += H.y * W.z; ACC[1][3] += H.y * W.w; \
    ACC[2][0] += H.z * W.x; ACC[2][1] += H.z * W.y; ACC[2][2] += H.z * W.z; ACC[2][3] += H.z * W.w; \
    ACC[3][0] += H.w * W.x; ACC[3][1] += H.w * W.y; ACC[3][2] += H.w * W.z; ACC[3][3] += H.w * W.w;

// ---------------- K5: GEMM1 pu[ks][e][f][m] = LN(si) . W1 ----------------
// grid (fc=8, e=8, ks=8) = 512 blocks, block 256.
// Explicit 4-deep LDG pipeline: wbuf[] stays architecturally live -> MLP>=4.
__global__ __launch_bounds__(256) void k5_gemm1(const float* __restrict__ W1,
                                                const float* __restrict__ gamma,
                                                const float* __restrict__ beta) {
    __shared__ float hs[128 * 8];
    int tid = threadIdx.x;
    int fc = blockIdx.x, e = blockIdx.y, ks = blockIdx.z;
    {   // stage 128 d x 8 m with LN applied
        int d = ks * 128 + (tid >> 1);
        int mb = (tid & 1) * 4;
        float4 v = *(const float4*)(g_si + ((size_t)e * DM + d) * 8 + mb);
        float4 mu = *(const float4*)(g_mean + e * 8 + mb);
        float4 rs = *(const float4*)(g_rstd + e * 8 + mb);
        float ga = gamma[d], be = beta[d];
        v.x = (v.x - mu.x) * rs.x * ga + be;
        v.y = (v.y - mu.y) * rs.y * ga + be;
        v.z = (v.z - mu.z) * rs.z * ga + be;
        v.w = (v.w - mu.w) * rs.w * ga + be;
        *(float4*)(hs + tid * 4) = v;
    }
    __syncthreads();
    int mh = tid >> 7;
    int fsl = tid & 127;
    int f0 = fc * 512 + fsl * 4;
    const float* wp = W1 + ((size_t)e * DM + ks * 128) * DF + f0;
    float acc[4][4];
#pragma unroll
    for (int i = 0; i < 4; i++)
#pragma unroll
        for (int j = 0; j < 4; j++) acc[i][j] = 0.f;

    float4 wbuf[4];
#pragma unroll
    for (int i = 0; i < 4; i++) wbuf[i] = *(const float4*)(wp + (size_t)i * DF);

#pragma unroll 1
    for (int chunk = 0; chunk < 31; chunk++) {
        int dd = chunk * 4;
        float4 w0 = wbuf[0], w1 = wbuf[1], w2 = wbuf[2], w3 = wbuf[3];
#pragma unroll
        for (int i = 0; i < 4; i++)
            wbuf[i] = *(const float4*)(wp + (size_t)(dd + 4 + i) * DF);
        float4 h0 = *(const float4*)(hs + (dd + 0) * 8 + mh * 4);
        float4 h1 = *(const float4*)(hs + (dd + 1) * 8 + mh * 4);
        float4 h2 = *(const float4*)(hs + (dd + 2) * 8 + mh * 4);
        float4 h3 = *(const float4*)(hs + (dd + 3) * 8 + mh * 4);
        TILE_FMA(acc, h0, w0)
        TILE_FMA(acc, h1, w1)
        TILE_FMA(acc, h2, w2)
        TILE_FMA(acc, h3, w3)
    }
    {   // epilogue: dd = 124..127
        float4 h0 = *(const float4*)(hs + 124 * 8 + mh * 4);
        float4 h1 = *(const float4*)(hs + 125 * 8 + mh * 4);
        float4 h2 = *(const float4*)(hs + 126 * 8 + mh * 4);
        float4 h3 = *(const float4*)(hs + 127 * 8 + mh * 4);
        TILE_FMA(acc, h0, wbuf[0])
        TILE_FMA(acc, h1, wbuf[1])
        TILE_FMA(acc, h2, wbuf[2])
        TILE_FMA(acc, h3, wbuf[3])
    }
    float* op = g_pu + ((size_t)(ks * NE + e) * DF + f0) * 8 + mh * 4;
#pragma unroll
    for (int j = 0; j < 4; j++)
        *(float4*)(op + j * 8) = make_float4(acc[0][j], acc[1][j], acc[2][j], acc[3][j]);
}

__device__ __forceinline__ float gelu_exact(float v) {
    return 0.5f * v * (1.0f + erff(v * 0.70710678118654752f));
}

// ---------------- K5b: GEMM2 pso[fs][e][d][m] = gelu(sum pu) . W2 ----------------
// grid (dc=2, e=8, fs=32) = 512 blocks; same explicit 4-deep pipeline.
__global__ __launch_bounds__(256) void k5b_gemm2(const float* __restrict__ W2) {
    __shared__ float us[128 * 8];
    int tid = threadIdx.x;
    int dc = blockIdx.x, e = blockIdx.y, fs = blockIdx.z;
    {   // stage u = gelu(sum of 8 k-split partials)
        int f = fs * 128 + (tid >> 1);
        int mb = (tid & 1) * 4;
        const float* pp = g_pu + ((size_t)e * DF + f) * 8 + mb;
        float4 s = *(const float4*)pp;
#pragma unroll
        for (int kq = 1; kq < KSPLIT; kq++) {
            float4 v = *(const float4*)(pp + (size_t)kq * NE * DF * 8);
            s.x += v.x; s.y += v.y; s.z += v.z; s.w += v.w;
        }
        float4 g;
        g.x = gelu_exact(s.x); g.y = gelu_exact(s.y);
        g.z = gelu_exact(s.z); g.w = gelu_exact(s.w);
        *(float4*)(us + tid * 4) = g;
    }
    __syncthreads();
    int mh = tid >> 7;
    int dsl = tid & 127;
    int d0 = dc * 512 + dsl * 4;
    const float* wp = W2 + ((size_t)e * DF + fs * 128) * DM + d0;
    float acc[4][4];
#pragma unroll
    for (int i = 0; i < 4; i++)
#pragma unroll
        for (int j = 0; j < 4; j++) acc[i][j] = 0.f;

    float4 wbuf[4];
#pragma unroll
    for (int i = 0; i < 4; i++) wbuf[i] = *(const float4*)(wp + (size_t)i * DM);

#pragma unroll 1
    for (int chunk = 0; chunk < 31; chunk++) {
        int ff = chunk * 4;
        float4 w0 = wbuf[0], w1 = wbuf[1], w2 = wbuf[2], w3 = wbuf[3];
#pragma unroll
        for (int i = 0; i < 4; i++)
            wbuf[i] = *(const float4*)(wp + (size_t)(ff + 4 + i) * DM);
        float4 u0 = *(const float4*)(us + (ff + 0) * 8 + mh * 4);
        float4 u1 = *(const float4*)(us + (ff + 1) * 8 + mh * 4);
        float4 u2 = *(const float4*)(us + (ff + 2) * 8 + mh * 4);
        float4 u3 = *(const float4*)(us + (ff + 3) * 8 + mh * 4);
        TILE_FMA(acc, u0, w0)
        TILE_FMA(acc, u1, w1)
        TILE_FMA(acc, u2, w2)
        TILE_FMA(acc, u3, w3)
    }
    {   // epilogue: ff = 124..127
        float4 u0 = *(const float4*)(us + 124 * 8 + mh * 4);
        float4 u1 = *(const float4*)(us + 125 * 8 + mh * 4);
        float4 u2 = *(const float4*)(us + 126 * 8 + mh * 4);
        float4 u3 = *(const float4*)(us + 127 * 8 + mh * 4);
        TILE_FMA(acc, u0, wbuf[0])
        TILE_FMA(acc, u1, wbuf[1])
        TILE_FMA(acc, u2, wbuf[2])
        TILE_FMA(acc, u3, wbuf[3])
    }
    float* op = g_pso + ((size_t)(fs * NE + e) * DM + d0) * 8 + mh * 4;
#pragma unroll
    for (int j = 0; j < 4; j++)
        *(float4*)(op + j * 8) = make_float4(acc[0][j], acc[1][j], acc[2][j], acc[3][j]);
}

// ---------------- K5c: reduce 32 f-split partials -> slot_out[b][n][d] ----------------
__global__ __launch_bounds__(128) void k5c_reduce() {
    int idx = blockIdx.x * 128 + threadIdx.x;  // 0..16383
    int e = idx >> 11;
    int rest = idx & 2047;
    int d = rest >> 1, mh = rest & 1;
    const float* pp = g_pso + ((size_t)e * DM + d) * 8 + mh * 4;
    float4 a = *(const float4*)pp;
#pragma unroll 8
    for (int fs = 1; fs < FSPLIT; fs++) {
        float4 v = *(const float4*)(pp + (size_t)fs * NE * DM * 8);
        a.x += v.x; a.y += v.y; a.z += v.z; a.w += v.w;
    }
    int m0 = mh * 4;
    float vals[4] = {a.x, a.y, a.z, a.w};
#pragma unroll
    for (int j = 0; j < 4; j++) {
        int m = m0 + j;
        int b = m >> 1, sl = m & 1;
        g_so[(size_t)(b * 16 + e * 2 + sl) * DM + d] = vals[j];
    }
}

// ---------------- K6: combine = softmax_n(logits) @ slot_out ----------------
__global__ __launch_bounds__(256) void k6_combine(float* __restrict__ out) {
    __shared__ float cs[64 * 16];
    int tc = blockIdx.x, b = blockIdx.y;
    int tid = threadIdx.x;
    int t0 = tc * 64;
    if (tid < 64) {
        const float* lp = g_logits + (size_t)(b * TT + t0 + tid) * NSLOT;
        float l[16];
#pragma unroll
        for (int n = 0; n < 16; n++) l[n] = lp[n];
        float m = l[0];
#pragma unroll
        for (int n = 1; n < 16; n++) m = fmaxf(m, l[n]);
        float sum = 0.f;
#pragma unroll
        for (int n = 0; n < 16; n++) { l[n] = expf(l[n] - m); sum += l[n]; }
        float inv = 1.0f / sum;
#pragma unroll
        for (int n = 0; n < 16; n++) cs[tid * 16 + n] = l[n] * inv;
    }
    __syncthreads();
    float4 sv[16];
    const float* sp = g_so + (size_t)b * 16 * DM + tid * 4;
#pragma unroll
    for (int n = 0; n < 16; n++) sv[n] = *(const float4*)(sp + (size_t)n * DM);
    float* op = out + (size_t)(b * TT + t0) * DM + tid * 4;
    for (int t = 0; t < 64; t++) {
        float4 acc = make_float4(0.f, 0.f, 0.f, 0.f);
#pragma unroll
        for (int n = 0; n < 16; n++) {
            float c = cs[t * 16 + n];
            acc.x += c * sv[n].x; acc.y += c * sv[n].y;
            acc.z += c * sv[n].z; acc.w += c * sv[n].w;
        }
        *(float4*)(op + (size_t)t * DM) = acc;
    }
}

// ---------------- launch ----------------
extern "C" void kernel_launch(void* const* d_in, const int* in_sizes, int n_in,
                              void* d_out, int out_size) {
    const float* x     = (const float*)d_in[0];
    const float* se    = (const float*)d_in[1];
    const float* W1    = (const float*)d_in[2];
    const float* W2    = (const float*)d_in[3];
    const float* gamma = (const float*)d_in[4];
    const float* beta  = (const float*)d_in[5];
    float* out = (float*)d_out;

    { dim3 g(NCHUNK, BB);        k13_fused<<<g, 256>>>(x, se); }
    { dim3 g(64, 4);             k4a_reduce<<<g, 256>>>(); }
    k4b_stats<<<1, 64>>>();
    { dim3 g(8, NE, KSPLIT);     k5_gemm1<<<g, 256>>>(W1, gamma, beta); }
    { dim3 g(2, NE, FSPLIT);     k5b_gemm2<<<g, 256>>>(W2); }
    k5c_reduce<<<128, 128>>>();
    { dim3 g(64, BB);            k6_combine<<<g, 256>>>(out); }
}

// round 13
// speedup vs baseline: 1.1592x; 1.0773x over previous
#include <cuda_runtime.h>
#include <math.h>

#define DM 1024
#define DF 4096
#define NE 8
#define NSLOT 16
#define BB 4
#define TT 4096
#define BT (BB*TT)
#define NCHUNK 64           // 64-token chunks per batch
#define CT 64               // tokens per chunk
#define KSPLIT 8            // k5: d-chunks of 128
#define FSPLIT 32           // k5b: f-chunks of 128

// ---------------- scratch (device globals, no allocation) ----------------
__device__ float g_logits[BT * NSLOT];                 // 1 MB
__device__ float g_csum_p[BB * NCHUNK * NSLOT];
__device__ float g_psum[BB * NCHUNK * NSLOT * DM];     // 16 MB  [b*64+tc][n][d]
__device__ float g_si[NE * DM * 8];                    // 256 KB [e][d][m]
__device__ float g_s1[64 * 4];
__device__ float g_s2[64 * 4];
__device__ float g_mean[NE * 8];
__device__ float g_rstd[NE * 8];
__device__ float g_pu[KSPLIT * NE * DF * 8];           // 8 MB   [ks][e][f][m]
__device__ float g_pso[FSPLIT * NE * DM * 8];          // 8 MB   [fs][e][d][m]
__device__ float g_so[BB * NSLOT * DM];                // 256 KB [b][n][d]

// ---------------- K13: fused logits + dispatch-softmax weighted sums ----------------
__global__ __launch_bounds__(256) void k13_fused(const float* __restrict__ x,
                                                 const float* __restrict__ se) {
    __shared__ float xs[CT * 65];
    __shared__ float ss[NSLOT * 64];
    __shared__ float ls[CT * NSLOT];
    __shared__ float ws[CT * NSLOT];
    int tid = threadIdx.x;
    int tc = blockIdx.x, b = blockIdx.y;
    int t0 = tc * CT;
    const float* xb = x + (size_t)(b * TT + t0) * DM;
    int tw = tid & 31, np = tid >> 5;
    float a00 = 0.f, a01 = 0.f, a10 = 0.f, a11 = 0.f;

    for (int dt = 0; dt < DM; dt += 64) {
        {
            int n = tid >> 4, dq = tid & 15;
            *(float4*)(ss + n * 64 + dq * 4) =
                *(const float4*)(se + (size_t)n * DM + dt + dq * 4);
        }
#pragma unroll
        for (int r = 0; r < 4; r++) {
            int idx = tid + 256 * r;
            int t = idx >> 4, dq = idx & 15;
            float4 v = *(const float4*)(xb + (size_t)t * DM + dt + dq * 4);
            float* p = xs + t * 65 + dq * 4;
            p[0] = v.x; p[1] = v.y; p[2] = v.z; p[3] = v.w;
        }
        __syncthreads();
#pragma unroll 8
        for (int d = 0; d < 64; d++) {
            float s0 = ss[(2 * np) * 64 + d];
            float s1 = ss[(2 * np + 1) * 64 + d];
            float x0 = xs[tw * 65 + d];
            float x1 = xs[(tw + 32) * 65 + d];
            a00 += x0 * s0; a01 += x0 * s1;
            a10 += x1 * s0; a11 += x1 * s1;
        }
        __syncthreads();
    }
    ls[tw * 16 + 2 * np]            = a00 * 0.03125f;
    ls[tw * 16 + 2 * np + 1]        = a01 * 0.03125f;
    ls[(tw + 32) * 16 + 2 * np]     = a10 * 0.03125f;
    ls[(tw + 32) * 16 + 2 * np + 1] = a11 * 0.03125f;
    __syncthreads();

    float* lg = g_logits + (size_t)(b * TT + t0) * NSLOT;
#pragma unroll
    for (int r = 0; r < 4; r++) {
        int idx = tid + 256 * r;
        float l = ls[idx];
        lg[idx] = l;
        ws[idx] = expf(l);
    }
    __syncthreads();

    if (tid < 16) {
        float s = 0.f;
        for (int t = 0; t < CT; t++) s += ws[t * 16 + tid];
        g_csum_p[(b * NCHUNK + tc) * 16 + tid] = s;
    }

    // Phase 2: weighted accumulation, prefetch distance 2 (x is L2-hot)
    float4 acc[16];
#pragma unroll
    for (int n = 0; n < 16; n++) acc[n] = make_float4(0.f, 0.f, 0.f, 0.f);
    const float* xp = xb + tid * 4;
    float4 xn0 = *(const float4*)xp;
    float4 xn1 = *(const float4*)(xp + DM);
#pragma unroll 1
    for (int t = 0; t < CT; t++) {
        float4 xv = xn0;
        xn0 = xn1;
        if (t + 2 < CT) xn1 = *(const float4*)(xp + (size_t)(t + 2) * DM);
#pragma unroll
        for (int n = 0; n < 16; n++) {
            float w = ws[t * 16 + n];
            acc[n].x += w * xv.x; acc[n].y += w * xv.y;
            acc[n].z += w * xv.z; acc[n].w += w * xv.w;
        }
    }
    float* op = g_psum + (size_t)(b * NCHUNK + tc) * 16 * DM + tid * 4;
#pragma unroll
    for (int n = 0; n < 16; n++)
        *(float4*)(op + (size_t)n * DM) = acc[n];
}

// ---------------- K4a: reduce partials, normalize, transpose, partial LN stats ----
__global__ __launch_bounds__(256) void k4a_reduce() {
    __shared__ float red[256];
    int bn = blockIdx.x, dc = blockIdx.y;
    int b = bn >> 4, n = bn & 15;
    int tid = threadIdx.x;
    if (tid < NCHUNK) red[tid] = g_csum_p[(b * NCHUNK + tid) * 16 + n];
    __syncthreads();
    if (tid == 0) {
        float s = 0.f;
        for (int i = 0; i < NCHUNK; i++) s += red[i];
        red[0] = 1.0f / s;
    }
    __syncthreads();
    float inv = red[0];
    __syncthreads();

    int d = dc * 256 + tid;
    const float* pp = g_psum + ((size_t)(b * NCHUNK) * 16 + n) * DM + d;
    float va = 0.f, vb = 0.f;
#pragma unroll 4
    for (int t = 0; t < NCHUNK; t += 2) {
        va += pp[(size_t)t * 16 * DM];
        vb += pp[(size_t)(t + 1) * 16 * DM];
    }
    float v = (va + vb) * inv;
    int e = n >> 1, sl = n & 1, m = (b << 1) | sl;
    g_si[((size_t)e * DM + d) * 8 + m] = v;

    red[tid] = v; __syncthreads();
    for (int s = 128; s > 0; s >>= 1) {
        if (tid < s) red[tid] += red[tid + s];
        __syncthreads();
    }
    float s1 = red[0]; __syncthreads();
    red[tid] = v * v; __syncthreads();
    for (int s = 128; s > 0; s >>= 1) {
        if (tid < s) red[tid] += red[tid + s];
        __syncthreads();
    }
    if (tid == 0) { g_s1[bn * 4 + dc] = s1; g_s2[bn * 4 + dc] = red[0]; }
}

// ---------------- K4b: finalize LN stats ----------------
__global__ void k4b_stats() {
    int bn = threadIdx.x;
    if (bn < 64) {
        float s1 = 0.f, s2 = 0.f;
#pragma unroll
        for (int q = 0; q < 4; q++) { s1 += g_s1[bn * 4 + q]; s2 += g_s2[bn * 4 + q]; }
        float mean = s1 * (1.0f / DM);
        float var = fmaxf(s2 * (1.0f / DM) - mean * mean, 0.f);
        int b = bn >> 4, n = bn & 15;
        int e = n >> 1, m = (b << 1) | (n & 1);
        g_mean[e * 8 + m] = mean;
        g_rstd[e * 8 + m] = rsqrtf(var + 1e-5f);
    }
}

// FMA micro-tile: 4 m-rows x 4 f-cols with one weight float4
#define TILE_FMA(ACC, H, W) \
    ACC[0][0] += H.x * W.x; ACC[0][1] += H.x * W.y; ACC[0][2] += H.x * W.z; ACC[0][3] += H.x * W.w; \
    ACC[1][0] += H.y * W.x; ACC[1][1] += H.y * W.y; ACC[1][2] += H.y * W.z; ACC[1][3] += H.y * W.w; \
    ACC[2][0] += H.z * W.x; ACC[2][1] += H.z * W.y; ACC[2][2] += H.z * W.z; ACC[2][3] += H.z * W.w; \
    ACC[3][0] += H.w * W.x; ACC[3][1] += H.w * W.y; ACC[3][2] += H.w * W.z; ACC[3][3] += H.w * W.w;

// Consume 4 weight rows (copied out of ring) against 4 staged rows of S
#define CONSUME4(ACC, S, ROW, MH, W0, W1, W2, W3) { \
    float4 _h0 = *(const float4*)((S) + ((ROW) + 0) * 8 + (MH) * 4); \
    float4 _h1 = *(const float4*)((S) + ((ROW) + 1) * 8 + (MH) * 4); \
    float4 _h2 = *(const float4*)((S) + ((ROW) + 2) * 8 + (MH) * 4); \
    float4 _h3 = *(const float4*)((S) + ((ROW) + 3) * 8 + (MH) * 4); \
    TILE_FMA(ACC, _h0, W0) \
    TILE_FMA(ACC, _h1, W1) \
    TILE_FMA(ACC, _h2, W2) \
    TILE_FMA(ACC, _h3, W3) }

// ---------------- K5: GEMM1 pu[ks][e][f][m] = LN(si) . W1 ----------------
// grid (fc=8, e=8, ks=8) = 512 blocks, block 256.
// Depth-8 LDG pipeline: ring of two 4-row float4 buffers, consume distance 2 chunks.
__global__ __launch_bounds__(256) void k5_gemm1(const float* __restrict__ W1,
                                                const float* __restrict__ gamma,
                                                const float* __restrict__ beta) {
    __shared__ float hs[128 * 8];
    int tid = threadIdx.x;
    int fc = blockIdx.x, e = blockIdx.y, ks = blockIdx.z;
    {   // stage 128 d x 8 m with LN applied
        int d = ks * 128 + (tid >> 1);
        int mb = (tid & 1) * 4;
        float4 v = *(const float4*)(g_si + ((size_t)e * DM + d) * 8 + mb);
        float4 mu = *(const float4*)(g_mean + e * 8 + mb);
        float4 rs = *(const float4*)(g_rstd + e * 8 + mb);
        float ga = gamma[d], be = beta[d];
        v.x = (v.x - mu.x) * rs.x * ga + be;
        v.y = (v.y - mu.y) * rs.y * ga + be;
        v.z = (v.z - mu.z) * rs.z * ga + be;
        v.w = (v.w - mu.w) * rs.w * ga + be;
        *(float4*)(hs + tid * 4) = v;
    }
    __syncthreads();
    int mh = tid >> 7;
    int fsl = tid & 127;
    int f0 = fc * 512 + fsl * 4;
    const float* wp = W1 + ((size_t)e * DM + ks * 128) * DF + f0;
    float acc[4][4];
#pragma unroll
    for (int i = 0; i < 4; i++)
#pragma unroll
        for (int j = 0; j < 4; j++) acc[i][j] = 0.f;

    float4 bufA[4], bufB[4];
#pragma unroll
    for (int i = 0; i < 4; i++) bufA[i] = *(const float4*)(wp + (size_t)i * DF);
#pragma unroll
    for (int i = 0; i < 4; i++) bufB[i] = *(const float4*)(wp + (size_t)(4 + i) * DF);

    // 32 chunks of 4 rows; steady state keeps 8 LDG.128 outstanding.
#pragma unroll 1
    for (int c = 0; c < 28; c += 2) {
        int rowA = c * 4, rowB = rowA + 4;
        float4 w0 = bufA[0], w1 = bufA[1], w2 = bufA[2], w3 = bufA[3];
#pragma unroll
        for (int i = 0; i < 4; i++)
            bufA[i] = *(const float4*)(wp + (size_t)(rowA + 8 + i) * DF);
        CONSUME4(acc, hs, rowA, mh, w0, w1, w2, w3)
        float4 v0 = bufB[0], v1 = bufB[1], v2 = bufB[2], v3 = bufB[3];
#pragma unroll
        for (int i = 0; i < 4; i++)
            bufB[i] = *(const float4*)(wp + (size_t)(rowB + 8 + i) * DF);
        CONSUME4(acc, hs, rowB, mh, v0, v1, v2, v3)
    }
    // epilogue: chunks 28..31 (rows 112..127), bufA=rows112-115, bufB=116-119
    {
        float4 w0 = bufA[0], w1 = bufA[1], w2 = bufA[2], w3 = bufA[3];
#pragma unroll
        for (int i = 0; i < 4; i++)
            bufA[i] = *(const float4*)(wp + (size_t)(120 + i) * DF);
        CONSUME4(acc, hs, 112, mh, w0, w1, w2, w3)
        float4 v0 = bufB[0], v1 = bufB[1], v2 = bufB[2], v3 = bufB[3];
#pragma unroll
        for (int i = 0; i < 4; i++)
            bufB[i] = *(const float4*)(wp + (size_t)(124 + i) * DF);
        CONSUME4(acc, hs, 116, mh, v0, v1, v2, v3)
        CONSUME4(acc, hs, 120, mh, bufA[0], bufA[1], bufA[2], bufA[3])
        CONSUME4(acc, hs, 124, mh, bufB[0], bufB[1], bufB[2], bufB[3])
    }
    float* op = g_pu + ((size_t)(ks * NE + e) * DF + f0) * 8 + mh * 4;
#pragma unroll
    for (int j = 0; j < 4; j++)
        *(float4*)(op + j * 8) = make_float4(acc[0][j], acc[1][j], acc[2][j], acc[3][j]);
}

__device__ __forceinline__ float gelu_exact(float v) {
    return 0.5f * v * (1.0f + erff(v * 0.70710678118654752f));
}

// ---------------- K5b: GEMM2 pso[fs][e][d][m] = gelu(sum pu) . W2 ----------------
// grid (dc=2, e=8, fs=32) = 512 blocks; same depth-8 pipeline.
__global__ __launch_bounds__(256) void k5b_gemm2(const float* __restrict__ W2) {
    __shared__ float us[128 * 8];
    int tid = threadIdx.x;
    int dc = blockIdx.x, e = blockIdx.y, fs = blockIdx.z;
    {   // stage u = gelu(sum of 8 k-split partials)
        int f = fs * 128 + (tid >> 1);
        int mb = (tid & 1) * 4;
        const float* pp = g_pu + ((size_t)e * DF + f) * 8 + mb;
        float4 s = *(const float4*)pp;
#pragma unroll
        for (int kq = 1; kq < KSPLIT; kq++) {
            float4 v = *(const float4*)(pp + (size_t)kq * NE * DF * 8);
            s.x += v.x; s.y += v.y; s.z += v.z; s.w += v.w;
        }
        float4 g;
        g.x = gelu_exact(s.x); g.y = gelu_exact(s.y);
        g.z = gelu_exact(s.z); g.w = gelu_exact(s.w);
        *(float4*)(us + tid * 4) = g;
    }
    __syncthreads();
    int mh = tid >> 7;
    int dsl = tid & 127;
    int d0 = dc * 512 + dsl * 4;
    const float* wp = W2 + ((size_t)e * DF + fs * 128) * DM + d0;
    float acc[4][4];
#pragma unroll
    for (int i = 0; i < 4; i++)
#pragma unroll
        for (int j = 0; j < 4; j++) acc[i][j] = 0.f;

    float4 bufA[4], bufB[4];
#pragma unroll
    for (int i = 0; i < 4; i++) bufA[i] = *(const float4*)(wp + (size_t)i * DM);
#pragma unroll
    for (int i = 0; i < 4; i++) bufB[i] = *(const float4*)(wp + (size_t)(4 + i) * DM);

#pragma unroll 1
    for (int c = 0; c < 28; c += 2) {
        int rowA = c * 4, rowB = rowA + 4;
        float4 w0 = bufA[0], w1 = bufA[1], w2 = bufA[2], w3 = bufA[3];
#pragma unroll
        for (int i = 0; i < 4; i++)
            bufA[i] = *(const float4*)(wp + (size_t)(rowA + 8 + i) * DM);
        CONSUME4(acc, us, rowA, mh, w0, w1, w2, w3)
        float4 v0 = bufB[0], v1 = bufB[1], v2 = bufB[2], v3 = bufB[3];
#pragma unroll
        for (int i = 0; i < 4; i++)
            bufB[i] = *(const float4*)(wp + (size_t)(rowB + 8 + i) * DM);
        CONSUME4(acc, us, rowB, mh, v0, v1, v2, v3)
    }
    {
        float4 w0 = bufA[0], w1 = bufA[1], w2 = bufA[2], w3 = bufA[3];
#pragma unroll
        for (int i = 0; i < 4; i++)
            bufA[i] = *(const float4*)(wp + (size_t)(120 + i) * DM);
        CONSUME4(acc, us, 112, mh, w0, w1, w2, w3)
        float4 v0 = bufB[0], v1 = bufB[1], v2 = bufB[2], v3 = bufB[3];
#pragma unroll
        for (int i = 0; i < 4; i++)
            bufB[i] = *(const float4*)(wp + (size_t)(124 + i) * DM);
        CONSUME4(acc, us, 116, mh, v0, v1, v2, v3)
        CONSUME4(acc, us, 120, mh, bufA[0], bufA[1], bufA[2], bufA[3])
        CONSUME4(acc, us, 124, mh, bufB[0], bufB[1], bufB[2], bufB[3])
    }
    float* op = g_pso + ((size_t)(fs * NE + e) * DM + d0) * 8 + mh * 4;
#pragma unroll
    for (int j = 0; j < 4; j++)
        *(float4*)(op + j * 8) = make_float4(acc[0][j], acc[1][j], acc[2][j], acc[3][j]);
}

// ---------------- K5c: reduce 32 f-split partials -> slot_out[b][n][d] ----------------
__global__ __launch_bounds__(128) void k5c_reduce() {
    int idx = blockIdx.x * 128 + threadIdx.x;  // 0..16383
    int e = idx >> 11;
    int rest = idx & 2047;
    int d = rest >> 1, mh = rest & 1;
    const float* pp = g_pso + ((size_t)e * DM + d) * 8 + mh * 4;
    float4 a = *(const float4*)pp;
#pragma unroll 8
    for (int fs = 1; fs < FSPLIT; fs++) {
        float4 v = *(const float4*)(pp + (size_t)fs * NE * DM * 8);
        a.x += v.x; a.y += v.y; a.z += v.z; a.w += v.w;
    }
    int m0 = mh * 4;
    float vals[4] = {a.x, a.y, a.z, a.w};
#pragma unroll
    for (int j = 0; j < 4; j++) {
        int m = m0 + j;
        int b = m >> 1, sl = m & 1;
        g_so[(size_t)(b * 16 + e * 2 + sl) * DM + d] = vals[j];
    }
}

// ---------------- K6: combine = softmax_n(logits) @ slot_out ----------------
__global__ __launch_bounds__(256) void k6_combine(float* __restrict__ out) {
    __shared__ float cs[64 * 16];
    int tc = blockIdx.x, b = blockIdx.y;
    int tid = threadIdx.x;
    int t0 = tc * 64;
    if (tid < 64) {
        const float* lp = g_logits + (size_t)(b * TT + t0 + tid) * NSLOT;
        float l[16];
#pragma unroll
        for (int n = 0; n < 16; n++) l[n] = lp[n];
        float m = l[0];
#pragma unroll
        for (int n = 1; n < 16; n++) m = fmaxf(m, l[n]);
        float sum = 0.f;
#pragma unroll
        for (int n = 0; n < 16; n++) { l[n] = expf(l[n] - m); sum += l[n]; }
        float inv = 1.0f / sum;
#pragma unroll
        for (int n = 0; n < 16; n++) cs[tid * 16 + n] = l[n] * inv;
    }
    __syncthreads();
    float4 sv[16];
    const float* sp = g_so + (size_t)b * 16 * DM + tid * 4;
#pragma unroll
    for (int n = 0; n < 16; n++) sv[n] = *(const float4*)(sp + (size_t)n * DM);
    float* op = out + (size_t)(b * TT + t0) * DM + tid * 4;
    for (int t = 0; t < 64; t++) {
        float4 acc = make_float4(0.f, 0.f, 0.f, 0.f);
#pragma unroll
        for (int n = 0; n < 16; n++) {
            float c = cs[t * 16 + n];
            acc.x += c * sv[n].x; acc.y += c * sv[n].y;
            acc.z += c * sv[n].z; acc.w += c * sv[n].w;
        }
        *(float4*)(op + (size_t)t * DM) = acc;
    }
}

// ---------------- launch ----------------
extern "C" void kernel_launch(void* const* d_in, const int* in_sizes, int n_in,
                              void* d_out, int out_size) {
    const float* x     = (const float*)d_in[0];
    const float* se    = (const float*)d_in[1];
    const float* W1    = (const float*)d_in[2];
    const float* W2    = (const float*)d_in[3];
    const float* gamma = (const float*)d_in[4];
    const float* beta  = (const float*)d_in[5];
    float* out = (float*)d_out;

    { dim3 g(NCHUNK, BB);        k13_fused<<<g, 256>>>(x, se); }
    { dim3 g(64, 4);             k4a_reduce<<<g, 256>>>(); }
    k4b_stats<<<1, 64>>>();
    { dim3 g(8, NE, KSPLIT);     k5_gemm1<<<g, 256>>>(W1, gamma, beta); }
    { dim3 g(2, NE, FSPLIT);     k5b_gemm2<<<g, 256>>>(W2); }
    k5c_reduce<<<128, 128>>>();
    { dim3 g(64, BB);            k6_combine<<<g, 256>>>(out); }
}

// round 14
// speedup vs baseline: 1.2265x; 1.0581x over previous
#include <cuda_runtime.h>
#include <math.h>

#define DM 1024
#define DF 4096
#define NE 8
#define NSLOT 16
#define BB 4
#define TT 4096
#define BT (BB*TT)
#define NCHUNK 64           // 64-token chunks per batch
#define CT 64               // tokens per chunk
#define KSPLIT 8            // k5: d-chunks of 128
#define FSPLIT 32           // k5b: f-chunks of 128

// ---------------- scratch (device globals, no allocation) ----------------
__device__ float g_logits[BT * NSLOT];                 // 1 MB
__device__ float g_csum_p[BB * NCHUNK * NSLOT];
__device__ float g_psum[BB * NCHUNK * NSLOT * DM];     // 16 MB  [b*64+tc][n][d]
__device__ float g_si[NE * DM * 8];                    // 256 KB [e][d][m]
__device__ float g_s1[64 * 4];
__device__ float g_s2[64 * 4];
__device__ float g_mean[NE * 8];
__device__ float g_rstd[NE * 8];
__device__ float g_pu[KSPLIT * NE * DF * 8];           // 8 MB   [ks][e][f][m]
__device__ float g_pso[FSPLIT * NE * DM * 8];          // 8 MB   [fs][e][d][m]
__device__ float g_so[BB * NSLOT * DM];                // 256 KB [b][n][d]

// ---------------- K13: fused logits + dispatch-softmax weighted sums ----------------
// Phase 1: 4tok x 4slot thread tile with 4-way d-split (2 FMA/LDS, bank-conflict-free).
__global__ __launch_bounds__(256) void k13_fused(const float* __restrict__ x,
                                                 const float* __restrict__ se) {
    __shared__ float xs[CT * 65];        // [64 tok][65] padded
    __shared__ float ss[NSLOT * 65];     // [16 slot][65] padded (stride 65 = 1 mod 32)
    __shared__ float ls[CT * NSLOT];
    __shared__ float ws[CT * NSLOT];
    int tid = threadIdx.x;
    int tc = blockIdx.x, b = blockIdx.y;
    int t0 = tc * CT;
    const float* xb = x + (size_t)(b * TT + t0) * DM;

    int pos = tid >> 2, q = tid & 3;     // 64 positions x 4 d-quarters
    int tokg = pos >> 2, slotg = pos & 3;
    float acc[4][4];
#pragma unroll
    for (int i = 0; i < 4; i++)
#pragma unroll
        for (int j = 0; j < 4; j++) acc[i][j] = 0.f;

    for (int dt = 0; dt < DM; dt += 64) {
        // stage slot tile [16][64] scalar into padded rows
#pragma unroll
        for (int r = 0; r < 4; r++) {
            int idx = tid + 256 * r;
            int n = idx >> 6, dd2 = idx & 63;
            ss[n * 65 + dd2] = se[(size_t)n * DM + dt + dd2];
        }
        // stage x tile [64][64] (padded rows of 65)
#pragma unroll
        for (int r = 0; r < 4; r++) {
            int idx = tid + 256 * r;
            int t = idx >> 4, dq = idx & 15;
            float4 v = *(const float4*)(xb + (size_t)t * DM + dt + dq * 4);
            float* p = xs + t * 65 + dq * 4;
            p[0] = v.x; p[1] = v.y; p[2] = v.z; p[3] = v.w;
        }
        __syncthreads();
#pragma unroll
        for (int dd = 0; dd < 16; dd++) {
            int d = dd * 4 + q;          // stride-4 interleave: lanes hit distinct banks
            float sv0 = ss[(slotg * 4 + 0) * 65 + d];
            float sv1 = ss[(slotg * 4 + 1) * 65 + d];
            float sv2 = ss[(slotg * 4 + 2) * 65 + d];
            float sv3 = ss[(slotg * 4 + 3) * 65 + d];
            float xv0 = xs[(tokg * 4 + 0) * 65 + d];
            float xv1 = xs[(tokg * 4 + 1) * 65 + d];
            float xv2 = xs[(tokg * 4 + 2) * 65 + d];
            float xv3 = xs[(tokg * 4 + 3) * 65 + d];
            acc[0][0] += xv0 * sv0; acc[0][1] += xv0 * sv1; acc[0][2] += xv0 * sv2; acc[0][3] += xv0 * sv3;
            acc[1][0] += xv1 * sv0; acc[1][1] += xv1 * sv1; acc[1][2] += xv1 * sv2; acc[1][3] += xv1 * sv3;
            acc[2][0] += xv2 * sv0; acc[2][1] += xv2 * sv1; acc[2][2] += xv2 * sv2; acc[2][3] += xv2 * sv3;
            acc[3][0] += xv3 * sv0; acc[3][1] += xv3 * sv1; acc[3][2] += xv3 * sv2; acc[3][3] += xv3 * sv3;
        }
        __syncthreads();
    }
    // reduce over the 4 d-quarter lanes (xor on q bits), q==0 writes
#pragma unroll
    for (int i = 0; i < 4; i++)
#pragma unroll
        for (int j = 0; j < 4; j++) {
            float v = acc[i][j];
            v += __shfl_xor_sync(0xFFFFFFFFu, v, 1);
            v += __shfl_xor_sync(0xFFFFFFFFu, v, 2);
            if (q == 0)
                ls[(tokg * 4 + i) * 16 + slotg * 4 + j] = v * 0.03125f;
        }
    __syncthreads();

    float* lg = g_logits + (size_t)(b * TT + t0) * NSLOT;
#pragma unroll
    for (int r = 0; r < 4; r++) {
        int idx = tid + 256 * r;
        float l = ls[idx];
        lg[idx] = l;
        ws[idx] = expf(l);
    }
    __syncthreads();

    if (tid < 16) {
        float s = 0.f;
        for (int t = 0; t < CT; t++) s += ws[t * 16 + tid];
        g_csum_p[(b * NCHUNK + tc) * 16 + tid] = s;
    }

    // Phase 2: weighted accumulation, prefetch distance 2 (x is L2-hot)
    float4 acc2[16];
#pragma unroll
    for (int n = 0; n < 16; n++) acc2[n] = make_float4(0.f, 0.f, 0.f, 0.f);
    const float* xp = xb + tid * 4;
    float4 xn0 = *(const float4*)xp;
    float4 xn1 = *(const float4*)(xp + DM);
#pragma unroll 1
    for (int t = 0; t < CT; t++) {
        float4 xv = xn0;
        xn0 = xn1;
        if (t + 2 < CT) xn1 = *(const float4*)(xp + (size_t)(t + 2) * DM);
#pragma unroll
        for (int n = 0; n < 16; n++) {
            float w = ws[t * 16 + n];
            acc2[n].x += w * xv.x; acc2[n].y += w * xv.y;
            acc2[n].z += w * xv.z; acc2[n].w += w * xv.w;
        }
    }
    float* op = g_psum + (size_t)(b * NCHUNK + tc) * 16 * DM + tid * 4;
#pragma unroll
    for (int n = 0; n < 16; n++)
        *(float4*)(op + (size_t)n * DM) = acc2[n];
}

// ---------------- K4a: reduce partials, normalize, transpose, partial LN stats ----
__global__ __launch_bounds__(256) void k4a_reduce() {
    __shared__ float red[256];
    int bn = blockIdx.x, dc = blockIdx.y;
    int b = bn >> 4, n = bn & 15;
    int tid = threadIdx.x;
    if (tid < NCHUNK) red[tid] = g_csum_p[(b * NCHUNK + tid) * 16 + n];
    __syncthreads();
    if (tid == 0) {
        float s = 0.f;
        for (int i = 0; i < NCHUNK; i++) s += red[i];
        red[0] = 1.0f / s;
    }
    __syncthreads();
    float inv = red[0];
    __syncthreads();

    int d = dc * 256 + tid;
    const float* pp = g_psum + ((size_t)(b * NCHUNK) * 16 + n) * DM + d;
    float va = 0.f, vb = 0.f;
#pragma unroll 4
    for (int t = 0; t < NCHUNK; t += 2) {
        va += pp[(size_t)t * 16 * DM];
        vb += pp[(size_t)(t + 1) * 16 * DM];
    }
    float v = (va + vb) * inv;
    int e = n >> 1, sl = n & 1, m = (b << 1) | sl;
    g_si[((size_t)e * DM + d) * 8 + m] = v;

    red[tid] = v; __syncthreads();
    for (int s = 128; s > 0; s >>= 1) {
        if (tid < s) red[tid] += red[tid + s];
        __syncthreads();
    }
    float s1 = red[0]; __syncthreads();
    red[tid] = v * v; __syncthreads();
    for (int s = 128; s > 0; s >>= 1) {
        if (tid < s) red[tid] += red[tid + s];
        __syncthreads();
    }
    if (tid == 0) { g_s1[bn * 4 + dc] = s1; g_s2[bn * 4 + dc] = red[0]; }
}

// ---------------- K4b: finalize LN stats ----------------
__global__ void k4b_stats() {
    int bn = threadIdx.x;
    if (bn < 64) {
        float s1 = 0.f, s2 = 0.f;
#pragma unroll
        for (int q = 0; q < 4; q++) { s1 += g_s1[bn * 4 + q]; s2 += g_s2[bn * 4 + q]; }
        float mean = s1 * (1.0f / DM);
        float var = fmaxf(s2 * (1.0f / DM) - mean * mean, 0.f);
        int b = bn >> 4, n = bn & 15;
        int e = n >> 1, m = (b << 1) | (n & 1);
        g_mean[e * 8 + m] = mean;
        g_rstd[e * 8 + m] = rsqrtf(var + 1e-5f);
    }
}

// FMA micro-tile: 4 m-rows x 4 f-cols with one weight float4
#define TILE_FMA(ACC, H, W) \
    ACC[0][0] += H.x * W.x; ACC[0][1] += H.x * W.y; ACC[0][2] += H.x * W.z; ACC[0][3] += H.x * W.w; \
    ACC[1][0] += H.y * W.x; ACC[1][1] += H.y * W.y; ACC[1][2] += H.y * W.z; ACC[1][3] += H.y * W.w; \
    ACC[2][0] += H.z * W.x; ACC[2][1] += H.z * W.y; ACC[2][2] += H.z * W.z; ACC[2][3] += H.z * W.w; \
    ACC[3][0] += H.w * W.x; ACC[3][1] += H.w * W.y; ACC[3][2] += H.w * W.z; ACC[3][3] += H.w * W.w;

// Consume 4 weight rows (copied out of ring) against 4 staged rows of S
#define CONSUME4(ACC, S, ROW, MH, W0, W1, W2, W3) { \
    float4 _h0 = *(const float4*)((S) + ((ROW) + 0) * 8 + (MH) * 4); \
    float4 _h1 = *(const float4*)((S) + ((ROW) + 1) * 8 + (MH) * 4); \
    float4 _h2 = *(const float4*)((S) + ((ROW) + 2) * 8 + (MH) * 4); \
    float4 _h3 = *(const float4*)((S) + ((ROW) + 3) * 8 + (MH) * 4); \
    TILE_FMA(ACC, _h0, W0) \
    TILE_FMA(ACC, _h1, W1) \
    TILE_FMA(ACC, _h2, W2) \
    TILE_FMA(ACC, _h3, W3) }

// ---------------- K5: GEMM1 pu[ks][e][f][m] = LN(si) . W1 ----------------
// grid (fc=8, e=8, ks=8) = 512 blocks, block 256. Depth-8 LDG pipeline.
__global__ __launch_bounds__(256) void k5_gemm1(const float* __restrict__ W1,
                                                const float* __restrict__ gamma,
                                                const float* __restrict__ beta) {
    __shared__ float hs[128 * 8];
    int tid = threadIdx.x;
    int fc = blockIdx.x, e = blockIdx.y, ks = blockIdx.z;
    {   // stage 128 d x 8 m with LN applied
        int d = ks * 128 + (tid >> 1);
        int mb = (tid & 1) * 4;
        float4 v = *(const float4*)(g_si + ((size_t)e * DM + d) * 8 + mb);
        float4 mu = *(const float4*)(g_mean + e * 8 + mb);
        float4 rs = *(const float4*)(g_rstd + e * 8 + mb);
        float ga = gamma[d], be = beta[d];
        v.x = (v.x - mu.x) * rs.x * ga + be;
        v.y = (v.y - mu.y) * rs.y * ga + be;
        v.z = (v.z - mu.z) * rs.z * ga + be;
        v.w = (v.w - mu.w) * rs.w * ga + be;
        *(float4*)(hs + tid * 4) = v;
    }
    __syncthreads();
    int mh = tid >> 7;
    int fsl = tid & 127;
    int f0 = fc * 512 + fsl * 4;
    const float* wp = W1 + ((size_t)e * DM + ks * 128) * DF + f0;
    float acc[4][4];
#pragma unroll
    for (int i = 0; i < 4; i++)
#pragma unroll
        for (int j = 0; j < 4; j++) acc[i][j] = 0.f;

    float4 bufA[4], bufB[4];
#pragma unroll
    for (int i = 0; i < 4; i++) bufA[i] = *(const float4*)(wp + (size_t)i * DF);
#pragma unroll
    for (int i = 0; i < 4; i++) bufB[i] = *(const float4*)(wp + (size_t)(4 + i) * DF);

#pragma unroll 1
    for (int c = 0; c < 28; c += 2) {
        int rowA = c * 4, rowB = rowA + 4;
        float4 w0 = bufA[0], w1 = bufA[1], w2 = bufA[2], w3 = bufA[3];
#pragma unroll
        for (int i = 0; i < 4; i++)
            bufA[i] = *(const float4*)(wp + (size_t)(rowA + 8 + i) * DF);
        CONSUME4(acc, hs, rowA, mh, w0, w1, w2, w3)
        float4 v0 = bufB[0], v1 = bufB[1], v2 = bufB[2], v3 = bufB[3];
#pragma unroll
        for (int i = 0; i < 4; i++)
            bufB[i] = *(const float4*)(wp + (size_t)(rowB + 8 + i) * DF);
        CONSUME4(acc, hs, rowB, mh, v0, v1, v2, v3)
    }
    {
        float4 w0 = bufA[0], w1 = bufA[1], w2 = bufA[2], w3 = bufA[3];
#pragma unroll
        for (int i = 0; i < 4; i++)
            bufA[i] = *(const float4*)(wp + (size_t)(120 + i) * DF);
        CONSUME4(acc, hs, 112, mh, w0, w1, w2, w3)
        float4 v0 = bufB[0], v1 = bufB[1], v2 = bufB[2], v3 = bufB[3];
#pragma unroll
        for (int i = 0; i < 4; i++)
            bufB[i] = *(const float4*)(wp + (size_t)(124 + i) * DF);
        CONSUME4(acc, hs, 116, mh, v0, v1, v2, v3)
        CONSUME4(acc, hs, 120, mh, bufA[0], bufA[1], bufA[2], bufA[3])
        CONSUME4(acc, hs, 124, mh, bufB[0], bufB[1], bufB[2], bufB[3])
    }
    float* op = g_pu + ((size_t)(ks * NE + e) * DF + f0) * 8 + mh * 4;
#pragma unroll
    for (int j = 0; j < 4; j++)
        *(float4*)(op + j * 8) = make_float4(acc[0][j], acc[1][j], acc[2][j], acc[3][j]);
}

__device__ __forceinline__ float gelu_exact(float v) {
    return 0.5f * v * (1.0f + erff(v * 0.70710678118654752f));
}

// ---------------- K5b: GEMM2 pso[fs][e][d][m] = gelu(sum pu) . W2 ----------------
// grid (dc=2, e=8, fs=32) = 512 blocks; same depth-8 pipeline.
__global__ __launch_bounds__(256) void k5b_gemm2(const float* __restrict__ W2) {
    __shared__ float us[128 * 8];
    int tid = threadIdx.x;
    int dc = blockIdx.x, e = blockIdx.y, fs = blockIdx.z;
    {   // stage u = gelu(sum of 8 k-split partials)
        int f = fs * 128 + (tid >> 1);
        int mb = (tid & 1) * 4;
        const float* pp = g_pu + ((size_t)e * DF + f) * 8 + mb;
        float4 s = *(const float4*)pp;
#pragma unroll
        for (int kq = 1; kq < KSPLIT; kq++) {
            float4 v = *(const float4*)(pp + (size_t)kq * NE * DF * 8);
            s.x += v.x; s.y += v.y; s.z += v.z; s.w += v.w;
        }
        float4 g;
        g.x = gelu_exact(s.x); g.y = gelu_exact(s.y);
        g.z = gelu_exact(s.z); g.w = gelu_exact(s.w);
        *(float4*)(us + tid * 4) = g;
    }
    __syncthreads();
    int mh = tid >> 7;
    int dsl = tid & 127;
    int d0 = dc * 512 + dsl * 4;
    const float* wp = W2 + ((size_t)e * DF + fs * 128) * DM + d0;
    float acc[4][4];
#pragma unroll
    for (int i = 0; i < 4; i++)
#pragma unroll
        for (int j = 0; j < 4; j++) acc[i][j] = 0.f;

    float4 bufA[4], bufB[4];
#pragma unroll
    for (int i = 0; i < 4; i++) bufA[i] = *(const float4*)(wp + (size_t)i * DM);
#pragma unroll
    for (int i = 0; i < 4; i++) bufB[i] = *(const float4*)(wp + (size_t)(4 + i) * DM);

#pragma unroll 1
    for (int c = 0; c < 28; c += 2) {
        int rowA = c * 4, rowB = rowA + 4;
        float4 w0 = bufA[0], w1 = bufA[1], w2 = bufA[2], w3 = bufA[3];
#pragma unroll
        for (int i = 0; i < 4; i++)
            bufA[i] = *(const float4*)(wp + (size_t)(rowA + 8 + i) * DM);
        CONSUME4(acc, us, rowA, mh, w0, w1, w2, w3)
        float4 v0 = bufB[0], v1 = bufB[1], v2 = bufB[2], v3 = bufB[3];
#pragma unroll
        for (int i = 0; i < 4; i++)
            bufB[i] = *(const float4*)(wp + (size_t)(rowB + 8 + i) * DM);
        CONSUME4(acc, us, rowB, mh, v0, v1, v2, v3)
    }
    {
        float4 w0 = bufA[0], w1 = bufA[1], w2 = bufA[2], w3 = bufA[3];
#pragma unroll
        for (int i = 0; i < 4; i++)
            bufA[i] = *(const float4*)(wp + (size_t)(120 + i) * DM);
        CONSUME4(acc, us, 112, mh, w0, w1, w2, w3)
        float4 v0 = bufB[0], v1 = bufB[1], v2 = bufB[2], v3 = bufB[3];
#pragma unroll
        for (int i = 0; i < 4; i++)
            bufB[i] = *(const float4*)(wp + (size_t)(124 + i) * DM);
        CONSUME4(acc, us, 116, mh, v0, v1, v2, v3)
        CONSUME4(acc, us, 120, mh, bufA[0], bufA[1], bufA[2], bufA[3])
        CONSUME4(acc, us, 124, mh, bufB[0], bufB[1], bufB[2], bufB[3])
    }
    float* op = g_pso + ((size_t)(fs * NE + e) * DM + d0) * 8 + mh * 4;
#pragma unroll
    for (int j = 0; j < 4; j++)
        *(float4*)(op + j * 8) = make_float4(acc[0][j], acc[1][j], acc[2][j], acc[3][j]);
}

// ---------------- K5c: reduce 32 f-split partials -> slot_out[b][n][d] ----------------
__global__ __launch_bounds__(128) void k5c_reduce() {
    int idx = blockIdx.x * 128 + threadIdx.x;  // 0..16383
    int e = idx >> 11;
    int rest = idx & 2047;
    int d = rest >> 1, mh = rest & 1;
    const float* pp = g_pso + ((size_t)e * DM + d) * 8 + mh * 4;
    float4 a = *(const float4*)pp;
#pragma unroll 8
    for (int fs = 1; fs < FSPLIT; fs++) {
        float4 v = *(const float4*)(pp + (size_t)fs * NE * DM * 8);
        a.x += v.x; a.y += v.y; a.z += v.z; a.w += v.w;
    }
    int m0 = mh * 4;
    float vals[4] = {a.x, a.y, a.z, a.w};
#pragma unroll
    for (int j = 0; j < 4; j++) {
        int m = m0 + j;
        int b = m >> 1, sl = m & 1;
        g_so[(size_t)(b * 16 + e * 2 + sl) * DM + d] = vals[j];
    }
}

// ---------------- K6: combine = softmax_n(logits) @ slot_out ----------------
__global__ __launch_bounds__(256) void k6_combine(float* __restrict__ out) {
    __shared__ float cs[64 * 16];
    int tc = blockIdx.x, b = blockIdx.y;
    int tid = threadIdx.x;
    int t0 = tc * 64;
    if (tid < 64) {
        const float* lp = g_logits + (size_t)(b * TT + t0 + tid) * NSLOT;
        float l[16];
#pragma unroll
        for (int n = 0; n < 16; n++) l[n] = lp[n];
        float m = l[0];
#pragma unroll
        for (int n = 1; n < 16; n++) m = fmaxf(m, l[n]);
        float sum = 0.f;
#pragma unroll
        for (int n = 0; n < 16; n++) { l[n] = expf(l[n] - m); sum += l[n]; }
        float inv = 1.0f / sum;
#pragma unroll
        for (int n = 0; n < 16; n++) cs[tid * 16 + n] = l[n] * inv;
    }
    __syncthreads();
    float4 sv[16];
    const float* sp = g_so + (size_t)b * 16 * DM + tid * 4;
#pragma unroll
    for (int n = 0; n < 16; n++) sv[n] = *(const float4*)(sp + (size_t)n * DM);
    float* op = out + (size_t)(b * TT + t0) * DM + tid * 4;
    for (int t = 0; t < 64; t++) {
        float4 acc = make_float4(0.f, 0.f, 0.f, 0.f);
#pragma unroll
        for (int n = 0; n < 16; n++) {
            float c = cs[t * 16 + n];
            acc.x += c * sv[n].x; acc.y += c * sv[n].y;
            acc.z += c * sv[n].z; acc.w += c * sv[n].w;
        }
        *(float4*)(op + (size_t)t * DM) = acc;
    }
}

// ---------------- launch ----------------
extern "C" void kernel_launch(void* const* d_in, const int* in_sizes, int n_in,
                              void* d_out, int out_size) {
    const float* x     = (const float*)d_in[0];
    const float* se    = (const float*)d_in[1];
    const float* W1    = (const float*)d_in[2];
    const float* W2    = (const float*)d_in[3];
    const float* gamma = (const float*)d_in[4];
    const float* beta  = (const float*)d_in[5];
    float* out = (float*)d_out;

    { dim3 g(NCHUNK, BB);        k13_fused<<<g, 256>>>(x, se); }
    { dim3 g(64, 4);             k4a_reduce<<<g, 256>>>(); }
    k4b_stats<<<1, 64>>>();
    { dim3 g(8, NE, KSPLIT);     k5_gemm1<<<g, 256>>>(W1, gamma, beta); }
    { dim3 g(2, NE, FSPLIT);     k5b_gemm2<<<g, 256>>>(W2); }
    k5c_reduce<<<128, 128>>>();
    { dim3 g(64, BB);            k6_combine<<<g, 256>>>(out); }
}

// round 15
// speedup vs baseline: 1.2432x; 1.0136x over previous
#include <cuda_runtime.h>
#include <math.h>

#define DM 1024
#define DF 4096
#define NE 8
#define NSLOT 16
#define BB 4
#define TT 4096
#define BT (BB*TT)
#define NCHUNK 64           // 64-token chunks per batch
#define CT 64               // tokens per chunk
#define KSPLIT 8            // k5: d-chunks of 128
#define FSPLIT 32           // k5b: f-chunks of 128

typedef unsigned long long u64t;

// ---- packed f32x2 helpers (sm_103a FFMA2 path; fp32-exact) ----
__device__ __forceinline__ u64t pk2(float a, float b) {
    u64t r; asm("mov.b64 %0, {%1, %2};" : "=l"(r) : "f"(a), "f"(b)); return r;
}
__device__ __forceinline__ u64t dup2f(float a) {
    u64t r; asm("mov.b64 %0, {%1, %1};" : "=l"(r) : "f"(a)); return r;
}
__device__ __forceinline__ void fma2(u64t& d, u64t a, u64t b) {
    asm("fma.rn.f32x2 %0, %1, %2, %0;" : "+l"(d) : "l"(a), "l"(b));
}
__device__ __forceinline__ float2 upk(u64t v) {
    float2 r; asm("mov.b64 {%0, %1}, %2;" : "=f"(r.x), "=f"(r.y) : "l"(v)); return r;
}

// ---------------- scratch (device globals, no allocation) ----------------
__device__ float g_logits[BT * NSLOT];                 // 1 MB
__device__ float g_csum_p[BB * NCHUNK * NSLOT];
__device__ float g_psum[BB * NCHUNK * NSLOT * DM];     // 16 MB  [b*64+tc][n][d]
__device__ float g_si[NE * DM * 8];                    // 256 KB [e][d][m]
__device__ float g_s1[64 * 4];
__device__ float g_s2[64 * 4];
__device__ float g_mean[NE * 8];
__device__ float g_rstd[NE * 8];
__device__ float g_pu[KSPLIT * NE * DF * 8];           // 8 MB   [ks][e][f][m]
__device__ float g_pso[FSPLIT * NE * DM * 8];          // 8 MB   [fs][e][d][m]
__device__ float g_so[BB * NSLOT * DM];                // 256 KB [b][n][d]

// ---------------- K13: fused logits + dispatch-softmax weighted sums ----------------
__global__ __launch_bounds__(256) void k13_fused(const float* __restrict__ x,
                                                 const float* __restrict__ se) {
    __shared__ float xs[CT * 65];        // [64 tok][65] padded
    __shared__ float ss[NSLOT * 65];     // [16 slot][65] padded
    __shared__ float ls[CT * NSLOT];
    __shared__ float ws[CT * NSLOT];
    int tid = threadIdx.x;
    int tc = blockIdx.x, b = blockIdx.y;
    int t0 = tc * CT;
    const float* xb = x + (size_t)(b * TT + t0) * DM;

    int pos = tid >> 2, q = tid & 3;     // 64 positions x 4 d-quarters
    int tokg = pos >> 2, slotg = pos & 3;
    u64t accp1[4][2];                    // [tok][slot-pair]
#pragma unroll
    for (int i = 0; i < 4; i++) { accp1[i][0] = 0ull; accp1[i][1] = 0ull; }

    for (int dt = 0; dt < DM; dt += 64) {
#pragma unroll
        for (int r = 0; r < 4; r++) {
            int idx = tid + 256 * r;
            int n = idx >> 6, dd2 = idx & 63;
            ss[n * 65 + dd2] = se[(size_t)n * DM + dt + dd2];
        }
#pragma unroll
        for (int r = 0; r < 4; r++) {
            int idx = tid + 256 * r;
            int t = idx >> 4, dq = idx & 15;
            float4 v = *(const float4*)(xb + (size_t)t * DM + dt + dq * 4);
            float* p = xs + t * 65 + dq * 4;
            p[0] = v.x; p[1] = v.y; p[2] = v.z; p[3] = v.w;
        }
        __syncthreads();
#pragma unroll
        for (int dd = 0; dd < 16; dd++) {
            int d = dd * 4 + q;
            u64t svp0 = pk2(ss[(slotg * 4 + 0) * 65 + d], ss[(slotg * 4 + 1) * 65 + d]);
            u64t svp1 = pk2(ss[(slotg * 4 + 2) * 65 + d], ss[(slotg * 4 + 3) * 65 + d]);
            float xv0 = xs[(tokg * 4 + 0) * 65 + d];
            float xv1 = xs[(tokg * 4 + 1) * 65 + d];
            float xv2 = xs[(tokg * 4 + 2) * 65 + d];
            float xv3 = xs[(tokg * 4 + 3) * 65 + d];
            u64t x0 = dup2f(xv0), x1 = dup2f(xv1), x2 = dup2f(xv2), x3 = dup2f(xv3);
            fma2(accp1[0][0], x0, svp0); fma2(accp1[0][1], x0, svp1);
            fma2(accp1[1][0], x1, svp0); fma2(accp1[1][1], x1, svp1);
            fma2(accp1[2][0], x2, svp0); fma2(accp1[2][1], x2, svp1);
            fma2(accp1[3][0], x3, svp0); fma2(accp1[3][1], x3, svp1);
        }
        __syncthreads();
    }
    // reduce over 4 d-quarter lanes, q==0 writes
#pragma unroll
    for (int i = 0; i < 4; i++)
#pragma unroll
        for (int jp = 0; jp < 2; jp++) {
            float2 v = upk(accp1[i][jp]);
            v.x += __shfl_xor_sync(0xFFFFFFFFu, v.x, 1);
            v.x += __shfl_xor_sync(0xFFFFFFFFu, v.x, 2);
            v.y += __shfl_xor_sync(0xFFFFFFFFu, v.y, 1);
            v.y += __shfl_xor_sync(0xFFFFFFFFu, v.y, 2);
            if (q == 0) {
                ls[(tokg * 4 + i) * 16 + slotg * 4 + jp * 2 + 0] = v.x * 0.03125f;
                ls[(tokg * 4 + i) * 16 + slotg * 4 + jp * 2 + 1] = v.y * 0.03125f;
            }
        }
    __syncthreads();

    float* lg = g_logits + (size_t)(b * TT + t0) * NSLOT;
#pragma unroll
    for (int r = 0; r < 4; r++) {
        int idx = tid + 256 * r;
        float l = ls[idx];
        lg[idx] = l;
        ws[idx] = expf(l);
    }
    __syncthreads();

    if (tid < 16) {
        float s = 0.f;
        for (int t = 0; t < CT; t++) s += ws[t * 16 + tid];
        g_csum_p[(b * NCHUNK + tc) * 16 + tid] = s;
    }

    // Phase 2: weighted accumulation, packed FMA, prefetch distance 2
    u64t accp2[16][2];
#pragma unroll
    for (int n = 0; n < 16; n++) { accp2[n][0] = 0ull; accp2[n][1] = 0ull; }
    const float* xp = xb + tid * 4;
    float4 xn0 = *(const float4*)xp;
    float4 xn1 = *(const float4*)(xp + DM);
#pragma unroll 1
    for (int t = 0; t < CT; t++) {
        float4 xv = xn0;
        xn0 = xn1;
        if (t + 2 < CT) xn1 = *(const float4*)(xp + (size_t)(t + 2) * DM);
        u64t xl = pk2(xv.x, xv.y), xh = pk2(xv.z, xv.w);
#pragma unroll
        for (int n = 0; n < 16; n++) {
            u64t wd = dup2f(ws[t * 16 + n]);
            fma2(accp2[n][0], xl, wd);
            fma2(accp2[n][1], xh, wd);
        }
    }
    float* op = g_psum + (size_t)(b * NCHUNK + tc) * 16 * DM + tid * 4;
#pragma unroll
    for (int n = 0; n < 16; n++) {
        float2 a = upk(accp2[n][0]), c = upk(accp2[n][1]);
        *(float4*)(op + (size_t)n * DM) = make_float4(a.x, a.y, c.x, c.y);
    }
}

// ---------------- K4a: reduce partials, normalize, transpose, partial LN stats ----
__global__ __launch_bounds__(256) void k4a_reduce() {
    __shared__ float red[256];
    int bn = blockIdx.x, dc = blockIdx.y;
    int b = bn >> 4, n = bn & 15;
    int tid = threadIdx.x;
    if (tid < NCHUNK) red[tid] = g_csum_p[(b * NCHUNK + tid) * 16 + n];
    __syncthreads();
    if (tid == 0) {
        float s = 0.f;
        for (int i = 0; i < NCHUNK; i++) s += red[i];
        red[0] = 1.0f / s;
    }
    __syncthreads();
    float inv = red[0];
    __syncthreads();

    int d = dc * 256 + tid;
    const float* pp = g_psum + ((size_t)(b * NCHUNK) * 16 + n) * DM + d;
    float va = 0.f, vb = 0.f;
#pragma unroll 4
    for (int t = 0; t < NCHUNK; t += 2) {
        va += pp[(size_t)t * 16 * DM];
        vb += pp[(size_t)(t + 1) * 16 * DM];
    }
    float v = (va + vb) * inv;
    int e = n >> 1, sl = n & 1, m = (b << 1) | sl;
    g_si[((size_t)e * DM + d) * 8 + m] = v;

    red[tid] = v; __syncthreads();
    for (int s = 128; s > 0; s >>= 1) {
        if (tid < s) red[tid] += red[tid + s];
        __syncthreads();
    }
    float s1 = red[0]; __syncthreads();
    red[tid] = v * v; __syncthreads();
    for (int s = 128; s > 0; s >>= 1) {
        if (tid < s) red[tid] += red[tid + s];
        __syncthreads();
    }
    if (tid == 0) { g_s1[bn * 4 + dc] = s1; g_s2[bn * 4 + dc] = red[0]; }
}

// ---------------- K4b: finalize LN stats ----------------
__global__ void k4b_stats() {
    int bn = threadIdx.x;
    if (bn < 64) {
        float s1 = 0.f, s2 = 0.f;
#pragma unroll
        for (int q = 0; q < 4; q++) { s1 += g_s1[bn * 4 + q]; s2 += g_s2[bn * 4 + q]; }
        float mean = s1 * (1.0f / DM);
        float var = fmaxf(s2 * (1.0f / DM) - mean * mean, 0.f);
        int b = bn >> 4, n = bn & 15;
        int e = n >> 1, m = (b << 1) | (n & 1);
        g_mean[e * 8 + m] = mean;
        g_rstd[e * 8 + m] = rsqrtf(var + 1e-5f);
    }
}

// Packed consume: one weight row (4 f cols) x 4 m rows = 8 f32x2 FMA
#define CONSUME1P(ACCP, S, ROW, MH, W) { \
    float4 _h = *(const float4*)((S) + (ROW) * 8 + (MH) * 4); \
    u64t _hl = pk2(_h.x, _h.y), _hh = pk2(_h.z, _h.w); \
    u64t _w0 = dup2f(W.x), _w1 = dup2f(W.y), _w2 = dup2f(W.z), _w3 = dup2f(W.w); \
    fma2(ACCP[0][0], _hl, _w0); fma2(ACCP[1][0], _hh, _w0); \
    fma2(ACCP[0][1], _hl, _w1); fma2(ACCP[1][1], _hh, _w1); \
    fma2(ACCP[0][2], _hl, _w2); fma2(ACCP[1][2], _hh, _w2); \
    fma2(ACCP[0][3], _hl, _w3); fma2(ACCP[1][3], _hh, _w3); }

#define CONSUME4P(ACCP, S, ROW, MH, W0, W1, W2, W3) { \
    CONSUME1P(ACCP, S, (ROW) + 0, MH, W0) \
    CONSUME1P(ACCP, S, (ROW) + 1, MH, W1) \
    CONSUME1P(ACCP, S, (ROW) + 2, MH, W2) \
    CONSUME1P(ACCP, S, (ROW) + 3, MH, W3) }

// ---------------- K5: GEMM1 pu[ks][e][f][m] = LN(si) . W1 ----------------
// grid (fc=8, e=8, ks=8) = 512 blocks; depth-8 LDG pipeline + packed FMA.
__global__ __launch_bounds__(256) void k5_gemm1(const float* __restrict__ W1,
                                                const float* __restrict__ gamma,
                                                const float* __restrict__ beta) {
    __shared__ float hs[128 * 8];
    int tid = threadIdx.x;
    int fc = blockIdx.x, e = blockIdx.y, ks = blockIdx.z;
    {   // stage 128 d x 8 m with LN applied
        int d = ks * 128 + (tid >> 1);
        int mb = (tid & 1) * 4;
        float4 v = *(const float4*)(g_si + ((size_t)e * DM + d) * 8 + mb);
        float4 mu = *(const float4*)(g_mean + e * 8 + mb);
        float4 rs = *(const float4*)(g_rstd + e * 8 + mb);
        float ga = gamma[d], be = beta[d];
        v.x = (v.x - mu.x) * rs.x * ga + be;
        v.y = (v.y - mu.y) * rs.y * ga + be;
        v.z = (v.z - mu.z) * rs.z * ga + be;
        v.w = (v.w - mu.w) * rs.w * ga + be;
        *(float4*)(hs + tid * 4) = v;
    }
    __syncthreads();
    int mh = tid >> 7;
    int fsl = tid & 127;
    int f0 = fc * 512 + fsl * 4;
    const float* wp = W1 + ((size_t)e * DM + ks * 128) * DF + f0;
    u64t accp[2][4];
#pragma unroll
    for (int i = 0; i < 2; i++)
#pragma unroll
        for (int j = 0; j < 4; j++) accp[i][j] = 0ull;

    float4 bufA[4], bufB[4];
#pragma unroll
    for (int i = 0; i < 4; i++) bufA[i] = *(const float4*)(wp + (size_t)i * DF);
#pragma unroll
    for (int i = 0; i < 4; i++) bufB[i] = *(const float4*)(wp + (size_t)(4 + i) * DF);

#pragma unroll 1
    for (int c = 0; c < 28; c += 2) {
        int rowA = c * 4, rowB = rowA + 4;
        float4 w0 = bufA[0], w1 = bufA[1], w2 = bufA[2], w3 = bufA[3];
#pragma unroll
        for (int i = 0; i < 4; i++)
            bufA[i] = *(const float4*)(wp + (size_t)(rowA + 8 + i) * DF);
        CONSUME4P(accp, hs, rowA, mh, w0, w1, w2, w3)
        float4 v0 = bufB[0], v1 = bufB[1], v2 = bufB[2], v3 = bufB[3];
#pragma unroll
        for (int i = 0; i < 4; i++)
            bufB[i] = *(const float4*)(wp + (size_t)(rowB + 8 + i) * DF);
        CONSUME4P(accp, hs, rowB, mh, v0, v1, v2, v3)
    }
    {
        float4 w0 = bufA[0], w1 = bufA[1], w2 = bufA[2], w3 = bufA[3];
#pragma unroll
        for (int i = 0; i < 4; i++)
            bufA[i] = *(const float4*)(wp + (size_t)(120 + i) * DF);
        CONSUME4P(accp, hs, 112, mh, w0, w1, w2, w3)
        float4 v0 = bufB[0], v1 = bufB[1], v2 = bufB[2], v3 = bufB[3];
#pragma unroll
        for (int i = 0; i < 4; i++)
            bufB[i] = *(const float4*)(wp + (size_t)(124 + i) * DF);
        CONSUME4P(accp, hs, 116, mh, v0, v1, v2, v3)
        CONSUME4P(accp, hs, 120, mh, bufA[0], bufA[1], bufA[2], bufA[3])
        CONSUME4P(accp, hs, 124, mh, bufB[0], bufB[1], bufB[2], bufB[3])
    }
    float* op = g_pu + ((size_t)(ks * NE + e) * DF + f0) * 8 + mh * 4;
#pragma unroll
    for (int j = 0; j < 4; j++) {
        float2 p0 = upk(accp[0][j]), p1 = upk(accp[1][j]);
        *(float4*)(op + j * 8) = make_float4(p0.x, p0.y, p1.x, p1.y);
    }
}

__device__ __forceinline__ float gelu_exact(float v) {
    return 0.5f * v * (1.0f + erff(v * 0.70710678118654752f));
}

// ---------------- K5b: GEMM2 pso[fs][e][d][m] = gelu(sum pu) . W2 ----------------
// grid (dc=2, e=8, fs=32) = 512 blocks; depth-8 pipeline + packed FMA.
__global__ __launch_bounds__(256) void k5b_gemm2(const float* __restrict__ W2) {
    __shared__ float us[128 * 8];
    int tid = threadIdx.x;
    int dc = blockIdx.x, e = blockIdx.y, fs = blockIdx.z;
    {   // stage u = gelu(sum of 8 k-split partials)
        int f = fs * 128 + (tid >> 1);
        int mb = (tid & 1) * 4;
        const float* pp = g_pu + ((size_t)e * DF + f) * 8 + mb;
        float4 s = *(const float4*)pp;
#pragma unroll
        for (int kq = 1; kq < KSPLIT; kq++) {
            float4 v = *(const float4*)(pp + (size_t)kq * NE * DF * 8);
            s.x += v.x; s.y += v.y; s.z += v.z; s.w += v.w;
        }
        float4 g;
        g.x = gelu_exact(s.x); g.y = gelu_exact(s.y);
        g.z = gelu_exact(s.z); g.w = gelu_exact(s.w);
        *(float4*)(us + tid * 4) = g;
    }
    __syncthreads();
    int mh = tid >> 7;
    int dsl = tid & 127;
    int d0 = dc * 512 + dsl * 4;
    const float* wp = W2 + ((size_t)e * DF + fs * 128) * DM + d0;
    u64t accp[2][4];
#pragma unroll
    for (int i = 0; i < 2; i++)
#pragma unroll
        for (int j = 0; j < 4; j++) accp[i][j] = 0ull;

    float4 bufA[4], bufB[4];
#pragma unroll
    for (int i = 0; i < 4; i++) bufA[i] = *(const float4*)(wp + (size_t)i * DM);
#pragma unroll
    for (int i = 0; i < 4; i++) bufB[i] = *(const float4*)(wp + (size_t)(4 + i) * DM);

#pragma unroll 1
    for (int c = 0; c < 28; c += 2) {
        int rowA = c * 4, rowB = rowA + 4;
        float4 w0 = bufA[0], w1 = bufA[1], w2 = bufA[2], w3 = bufA[3];
#pragma unroll
        for (int i = 0; i < 4; i++)
            bufA[i] = *(const float4*)(wp + (size_t)(rowA + 8 + i) * DM);
        CONSUME4P(accp, us, rowA, mh, w0, w1, w2, w3)
        float4 v0 = bufB[0], v1 = bufB[1], v2 = bufB[2], v3 = bufB[3];
#pragma unroll
        for (int i = 0; i < 4; i++)
            bufB[i] = *(const float4*)(wp + (size_t)(rowB + 8 + i) * DM);
        CONSUME4P(accp, us, rowB, mh, v0, v1, v2, v3)
    }
    {
        float4 w0 = bufA[0], w1 = bufA[1], w2 = bufA[2], w3 = bufA[3];
#pragma unroll
        for (int i = 0; i < 4; i++)
            bufA[i] = *(const float4*)(wp + (size_t)(120 + i) * DM);
        CONSUME4P(accp, us, 112, mh, w0, w1, w2, w3)
        float4 v0 = bufB[0], v1 = bufB[1], v2 = bufB[2], v3 = bufB[3];
#pragma unroll
        for (int i = 0; i < 4; i++)
            bufB[i] = *(const float4*)(wp + (size_t)(124 + i) * DM);
        CONSUME4P(accp, us, 116, mh, v0, v1, v2, v3)
        CONSUME4P(accp, us, 120, mh, bufA[0], bufA[1], bufA[2], bufA[3])
        CONSUME4P(accp, us, 124, mh, bufB[0], bufB[1], bufB[2], bufB[3])
    }
    float* op = g_pso + ((size_t)(fs * NE + e) * DM + d0) * 8 + mh * 4;
#pragma unroll
    for (int j = 0; j < 4; j++) {
        float2 p0 = upk(accp[0][j]), p1 = upk(accp[1][j]);
        *(float4*)(op + j * 8) = make_float4(p0.x, p0.y, p1.x, p1.y);
    }
}

// ---------------- K5c: reduce 32 f-split partials -> slot_out[b][n][d] ----------------
__global__ __launch_bounds__(128) void k5c_reduce() {
    int idx = blockIdx.x * 128 + threadIdx.x;  // 0..16383
    int e = idx >> 11;
    int rest = idx & 2047;
    int d = rest >> 1, mh = rest & 1;
    const float* pp = g_pso + ((size_t)e * DM + d) * 8 + mh * 4;
    float4 a = *(const float4*)pp;
#pragma unroll 8
    for (int fs = 1; fs < FSPLIT; fs++) {
        float4 v = *(const float4*)(pp + (size_t)fs * NE * DM * 8);
        a.x += v.x; a.y += v.y; a.z += v.z; a.w += v.w;
    }
    int m0 = mh * 4;
    float vals[4] = {a.x, a.y, a.z, a.w};
#pragma unroll
    for (int j = 0; j < 4; j++) {
        int m = m0 + j;
        int b = m >> 1, sl = m & 1;
        g_so[(size_t)(b * 16 + e * 2 + sl) * DM + d] = vals[j];
    }
}

// ---------------- K6: combine = softmax_n(logits) @ slot_out ----------------
__global__ __launch_bounds__(256) void k6_combine(float* __restrict__ out) {
    __shared__ float cs[64 * 16];
    int tc = blockIdx.x, b = blockIdx.y;
    int tid = threadIdx.x;
    int t0 = tc * 64;
    if (tid < 64) {
        const float* lp = g_logits + (size_t)(b * TT + t0 + tid) * NSLOT;
        float l[16];
#pragma unroll
        for (int n = 0; n < 16; n++) l[n] = lp[n];
        float m = l[0];
#pragma unroll
        for (int n = 1; n < 16; n++) m = fmaxf(m, l[n]);
        float sum = 0.f;
#pragma unroll
        for (int n = 0; n < 16; n++) { l[n] = expf(l[n] - m); sum += l[n]; }
        float inv = 1.0f / sum;
#pragma unroll
        for (int n = 0; n < 16; n++) cs[tid * 16 + n] = l[n] * inv;
    }
    __syncthreads();
    u64t svp[16][2];
    const float* sp = g_so + (size_t)b * 16 * DM + tid * 4;
#pragma unroll
    for (int n = 0; n < 16; n++) {
        float4 v = *(const float4*)(sp + (size_t)n * DM);
        svp[n][0] = pk2(v.x, v.y);
        svp[n][1] = pk2(v.z, v.w);
    }
    float* op = out + (size_t)(b * TT + t0) * DM + tid * 4;
    for (int t = 0; t < 64; t++) {
        u64t a0 = 0ull, a1 = 0ull;
#pragma unroll
        for (int n = 0; n < 16; n++) {
            u64t cd = dup2f(cs[t * 16 + n]);
            fma2(a0, svp[n][0], cd);
            fma2(a1, svp[n][1], cd);
        }
        float2 p0 = upk(a0), p1 = upk(a1);
        *(float4*)(op + (size_t)t * DM) = make_float4(p0.x, p0.y, p1.x, p1.y);
    }
}

// ---------------- launch ----------------
extern "C" void kernel_launch(void* const* d_in, const int* in_sizes, int n_in,
                              void* d_out, int out_size) {
    const float* x     = (const float*)d_in[0];
    const float* se    = (const float*)d_in[1];
    const float* W1    = (const float*)d_in[2];
    const float* W2    = (const float*)d_in[3];
    const float* gamma = (const float*)d_in[4];
    const float* beta  = (const float*)d_in[5];
    float* out = (float*)d_out;

    { dim3 g(NCHUNK, BB);        k13_fused<<<g, 256>>>(x, se); }
    { dim3 g(64, 4);             k4a_reduce<<<g, 256>>>(); }
    k4b_stats<<<1, 64>>>();
    { dim3 g(8, NE, KSPLIT);     k5_gemm1<<<g, 256>>>(W1, gamma, beta); }
    { dim3 g(2, NE, FSPLIT);     k5b_gemm2<<<g, 256>>>(W2); }
    k5c_reduce<<<128, 128>>>();
    { dim3 g(64, BB);            k6_combine<<<g, 256>>>(out); }
}

// round 16
// speedup vs baseline: 1.2937x; 1.0406x over previous
#include <cuda_runtime.h>
#include <math.h>

#define DM 1024
#define DF 4096
#define NE 8
#define NSLOT 16
#define BB 4
#define TT 4096
#define BT (BB*TT)
#define NCHUNK 64           // 64-token chunks per batch
#define CT 64               // tokens per chunk
#define KSPLIT 8            // k5: d-chunks of 128
#define FSPLIT 32           // k5b: f-chunks of 128

typedef unsigned long long u64t;

// ---- packed f32x2 helpers (sm_103a FFMA2 path; fp32-exact) ----
__device__ __forceinline__ u64t pk2(float a, float b) {
    u64t r; asm("mov.b64 %0, {%1, %2};" : "=l"(r) : "f"(a), "f"(b)); return r;
}
__device__ __forceinline__ u64t dup2f(float a) {
    u64t r; asm("mov.b64 %0, {%1, %1};" : "=l"(r) : "f"(a)); return r;
}
__device__ __forceinline__ void fma2(u64t& d, u64t a, u64t b) {
    asm("fma.rn.f32x2 %0, %1, %2, %0;" : "+l"(d) : "l"(a), "l"(b));
}
__device__ __forceinline__ float2 upk(u64t v) {
    float2 r; asm("mov.b64 {%0, %1}, %2;" : "=f"(r.x), "=f"(r.y) : "l"(v)); return r;
}

// ---- cp.async helpers ----
__device__ __forceinline__ void cp16(void* smem_dst, const void* gsrc) {
    unsigned s = (unsigned)__cvta_generic_to_shared(smem_dst);
    asm volatile("cp.async.cg.shared.global [%0], [%1], 16;" :: "r"(s), "l"(gsrc));
}
#define CP_COMMIT() asm volatile("cp.async.commit_group;")
#define CP_WAIT1()  asm volatile("cp.async.wait_group 1;" ::: "memory")

// ---------------- scratch (device globals, no allocation) ----------------
__device__ float g_logits[BT * NSLOT];                 // 1 MB
__device__ float g_csum_p[BB * NCHUNK * NSLOT];
__device__ float g_psum[BB * NCHUNK * NSLOT * DM];     // 16 MB  [b*64+tc][n][d]
__device__ float g_si[NE * DM * 8];                    // 256 KB [e][d][m]
__device__ float g_s1[64 * 4];
__device__ float g_s2[64 * 4];
__device__ float g_mean[NE * 8];
__device__ float g_rstd[NE * 8];
__device__ float g_pu[KSPLIT * NE * DF * 8];           // 8 MB   [ks][e][f][m]
__device__ float g_pso[FSPLIT * NE * DM * 8];          // 8 MB   [fs][e][d][m]
__device__ float g_so[BB * NSLOT * DM];                // 256 KB [b][n][d]

// ---------------- K13: fused logits + dispatch-softmax weighted sums ----------------
__global__ __launch_bounds__(256) void k13_fused(const float* __restrict__ x,
                                                 const float* __restrict__ se) {
    __shared__ float xs[CT * 65];        // [64 tok][65] padded
    __shared__ float ss[NSLOT * 65];     // [16 slot][65] padded
    __shared__ float ls[CT * NSLOT];
    __shared__ float ws[CT * NSLOT];
    int tid = threadIdx.x;
    int tc = blockIdx.x, b = blockIdx.y;
    int t0 = tc * CT;
    const float* xb = x + (size_t)(b * TT + t0) * DM;

    int pos = tid >> 2, q = tid & 3;     // 64 positions x 4 d-quarters
    int tokg = pos >> 2, slotg = pos & 3;
    u64t accp1[4][2];
#pragma unroll
    for (int i = 0; i < 4; i++) { accp1[i][0] = 0ull; accp1[i][1] = 0ull; }

    for (int dt = 0; dt < DM; dt += 64) {
#pragma unroll
        for (int r = 0; r < 4; r++) {
            int idx = tid + 256 * r;
            int n = idx >> 6, dd2 = idx & 63;
            ss[n * 65 + dd2] = se[(size_t)n * DM + dt + dd2];
        }
#pragma unroll
        for (int r = 0; r < 4; r++) {
            int idx = tid + 256 * r;
            int t = idx >> 4, dq = idx & 15;
            float4 v = *(const float4*)(xb + (size_t)t * DM + dt + dq * 4);
            float* p = xs + t * 65 + dq * 4;
            p[0] = v.x; p[1] = v.y; p[2] = v.z; p[3] = v.w;
        }
        __syncthreads();
#pragma unroll
        for (int dd = 0; dd < 16; dd++) {
            int d = dd * 4 + q;
            u64t svp0 = pk2(ss[(slotg * 4 + 0) * 65 + d], ss[(slotg * 4 + 1) * 65 + d]);
            u64t svp1 = pk2(ss[(slotg * 4 + 2) * 65 + d], ss[(slotg * 4 + 3) * 65 + d]);
            u64t x0 = dup2f(xs[(tokg * 4 + 0) * 65 + d]);
            u64t x1 = dup2f(xs[(tokg * 4 + 1) * 65 + d]);
            u64t x2 = dup2f(xs[(tokg * 4 + 2) * 65 + d]);
            u64t x3 = dup2f(xs[(tokg * 4 + 3) * 65 + d]);
            fma2(accp1[0][0], x0, svp0); fma2(accp1[0][1], x0, svp1);
            fma2(accp1[1][0], x1, svp0); fma2(accp1[1][1], x1, svp1);
            fma2(accp1[2][0], x2, svp0); fma2(accp1[2][1], x2, svp1);
            fma2(accp1[3][0], x3, svp0); fma2(accp1[3][1], x3, svp1);
        }
        __syncthreads();
    }
#pragma unroll
    for (int i = 0; i < 4; i++)
#pragma unroll
        for (int jp = 0; jp < 2; jp++) {
            float2 v = upk(accp1[i][jp]);
            v.x += __shfl_xor_sync(0xFFFFFFFFu, v.x, 1);
            v.x += __shfl_xor_sync(0xFFFFFFFFu, v.x, 2);
            v.y += __shfl_xor_sync(0xFFFFFFFFu, v.y, 1);
            v.y += __shfl_xor_sync(0xFFFFFFFFu, v.y, 2);
            if (q == 0) {
                ls[(tokg * 4 + i) * 16 + slotg * 4 + jp * 2 + 0] = v.x * 0.03125f;
                ls[(tokg * 4 + i) * 16 + slotg * 4 + jp * 2 + 1] = v.y * 0.03125f;
            }
        }
    __syncthreads();

    float* lg = g_logits + (size_t)(b * TT + t0) * NSLOT;
#pragma unroll
    for (int r = 0; r < 4; r++) {
        int idx = tid + 256 * r;
        float l = ls[idx];
        lg[idx] = l;
        ws[idx] = expf(l);
    }
    __syncthreads();

    if (tid < 16) {
        float s = 0.f;
        for (int t = 0; t < CT; t++) s += ws[t * 16 + tid];
        g_csum_p[(b * NCHUNK + tc) * 16 + tid] = s;
    }

    u64t accp2[16][2];
#pragma unroll
    for (int n = 0; n < 16; n++) { accp2[n][0] = 0ull; accp2[n][1] = 0ull; }
    const float* xp = xb + tid * 4;
    float4 xn0 = *(const float4*)xp;
    float4 xn1 = *(const float4*)(xp + DM);
#pragma unroll 1
    for (int t = 0; t < CT; t++) {
        float4 xv = xn0;
        xn0 = xn1;
        if (t + 2 < CT) xn1 = *(const float4*)(xp + (size_t)(t + 2) * DM);
        u64t xl = pk2(xv.x, xv.y), xh = pk2(xv.z, xv.w);
#pragma unroll
        for (int n = 0; n < 16; n++) {
            u64t wd = dup2f(ws[t * 16 + n]);
            fma2(accp2[n][0], xl, wd);
            fma2(accp2[n][1], xh, wd);
        }
    }
    float* op = g_psum + (size_t)(b * NCHUNK + tc) * 16 * DM + tid * 4;
#pragma unroll
    for (int n = 0; n < 16; n++) {
        float2 a = upk(accp2[n][0]), c = upk(accp2[n][1]);
        *(float4*)(op + (size_t)n * DM) = make_float4(a.x, a.y, c.x, c.y);
    }
}

// ---------------- K4a: reduce partials, normalize, transpose, partial LN stats ----
__global__ __launch_bounds__(256) void k4a_reduce() {
    __shared__ float red[256];
    int bn = blockIdx.x, dc = blockIdx.y;
    int b = bn >> 4, n = bn & 15;
    int tid = threadIdx.x;
    if (tid < NCHUNK) red[tid] = g_csum_p[(b * NCHUNK + tid) * 16 + n];
    __syncthreads();
    if (tid == 0) {
        float s = 0.f;
        for (int i = 0; i < NCHUNK; i++) s += red[i];
        red[0] = 1.0f / s;
    }
    __syncthreads();
    float inv = red[0];
    __syncthreads();

    int d = dc * 256 + tid;
    const float* pp = g_psum + ((size_t)(b * NCHUNK) * 16 + n) * DM + d;
    float va = 0.f, vb = 0.f;
#pragma unroll 4
    for (int t = 0; t < NCHUNK; t += 2) {
        va += pp[(size_t)t * 16 * DM];
        vb += pp[(size_t)(t + 1) * 16 * DM];
    }
    float v = (va + vb) * inv;
    int e = n >> 1, sl = n & 1, m = (b << 1) | sl;
    g_si[((size_t)e * DM + d) * 8 + m] = v;

    red[tid] = v; __syncthreads();
    for (int s = 128; s > 0; s >>= 1) {
        if (tid < s) red[tid] += red[tid + s];
        __syncthreads();
    }
    float s1 = red[0]; __syncthreads();
    red[tid] = v * v; __syncthreads();
    for (int s = 128; s > 0; s >>= 1) {
        if (tid < s) red[tid] += red[tid + s];
        __syncthreads();
    }
    if (tid == 0) { g_s1[bn * 4 + dc] = s1; g_s2[bn * 4 + dc] = red[0]; }
}

// ---------------- K4b: finalize LN stats ----------------
__global__ void k4b_stats() {
    int bn = threadIdx.x;
    if (bn < 64) {
        float s1 = 0.f, s2 = 0.f;
#pragma unroll
        for (int q = 0; q < 4; q++) { s1 += g_s1[bn * 4 + q]; s2 += g_s2[bn * 4 + q]; }
        float mean = s1 * (1.0f / DM);
        float var = fmaxf(s2 * (1.0f / DM) - mean * mean, 0.f);
        int b = bn >> 4, n = bn & 15;
        int e = n >> 1, m = (b << 1) | (n & 1);
        g_mean[e * 8 + m] = mean;
        g_rstd[e * 8 + m] = rsqrtf(var + 1e-5f);
    }
}

// Packed consume: one weight row (4 cols) x 4 m rows = 8 f32x2 FMA
#define CONSUME1P(ACCP, S, ROW, MH, W) { \
    float4 _h = *(const float4*)((S) + (ROW) * 8 + (MH) * 4); \
    u64t _hl = pk2(_h.x, _h.y), _hh = pk2(_h.z, _h.w); \
    u64t _w0 = dup2f(W.x), _w1 = dup2f(W.y), _w2 = dup2f(W.z), _w3 = dup2f(W.w); \
    fma2(ACCP[0][0], _hl, _w0); fma2(ACCP[1][0], _hh, _w0); \
    fma2(ACCP[0][1], _hl, _w1); fma2(ACCP[1][1], _hh, _w1); \
    fma2(ACCP[0][2], _hl, _w2); fma2(ACCP[1][2], _hh, _w2); \
    fma2(ACCP[0][3], _hl, _w3); fma2(ACCP[1][3], _hh, _w3); }

// ---------------- K5: GEMM1 pu[ks][e][f][m] = LN(si) . W1 ----------------
// grid (fc=8, e=8, ks=8) = 512 blocks, block 256.
// cp.async double-buffered weight staging: 16 KB tiles (8 rows x 512 f), L1-bypass.
__global__ __launch_bounds__(256) void k5_gemm1(const float* __restrict__ W1,
                                                const float* __restrict__ gamma,
                                                const float* __restrict__ beta) {
    __shared__ float hs[128 * 8];
    __shared__ __align__(16) float wt[2][8 * 512];   // 32 KB
    int tid = threadIdx.x;
    int fc = blockIdx.x, e = blockIdx.y, ks = blockIdx.z;
    {   // stage 128 d x 8 m with LN applied
        int d = ks * 128 + (tid >> 1);
        int mb = (tid & 1) * 4;
        float4 v = *(const float4*)(g_si + ((size_t)e * DM + d) * 8 + mb);
        float4 mu = *(const float4*)(g_mean + e * 8 + mb);
        float4 rs = *(const float4*)(g_rstd + e * 8 + mb);
        float ga = gamma[d], be = beta[d];
        v.x = (v.x - mu.x) * rs.x * ga + be;
        v.y = (v.y - mu.y) * rs.y * ga + be;
        v.z = (v.z - mu.z) * rs.z * ga + be;
        v.w = (v.w - mu.w) * rs.w * ga + be;
        *(float4*)(hs + tid * 4) = v;
    }
    int mh = tid >> 7;
    int fsl = tid & 127;
    const float* wbase = W1 + ((size_t)e * DM + ks * 128) * DF + fc * 512;

    // issue tile 0
#pragma unroll
    for (int i = 0; i < 4; i++) {
        int chunk = i * 256 + tid;              // 0..1023
        int row = chunk >> 7, col = chunk & 127;
        cp16(&wt[0][row * 512 + col * 4], wbase + (size_t)row * DF + col * 4);
    }
    CP_COMMIT();

    u64t accp[2][4];
#pragma unroll
    for (int i = 0; i < 2; i++)
#pragma unroll
        for (int j = 0; j < 4; j++) accp[i][j] = 0ull;

#pragma unroll 1
    for (int c = 0; c < 16; c++) {
        if (c + 1 < 16) {
            const float* src = wbase + (size_t)(c + 1) * 8 * DF;
            float* dst = wt[(c + 1) & 1];
#pragma unroll
            for (int i = 0; i < 4; i++) {
                int chunk = i * 256 + tid;
                int row = chunk >> 7, col = chunk & 127;
                cp16(&dst[row * 512 + col * 4], src + (size_t)row * DF + col * 4);
            }
        }
        CP_COMMIT();
        CP_WAIT1();
        __syncthreads();
        const float* wts = wt[c & 1];
#pragma unroll
        for (int r = 0; r < 8; r++) {
            float4 w = *(const float4*)(wts + r * 512 + fsl * 4);
            CONSUME1P(accp, hs, c * 8 + r, mh, w)
        }
        __syncthreads();
    }
    int f0 = fc * 512 + fsl * 4;
    float* op = g_pu + ((size_t)(ks * NE + e) * DF + f0) * 8 + mh * 4;
#pragma unroll
    for (int j = 0; j < 4; j++) {
        float2 p0 = upk(accp[0][j]), p1 = upk(accp[1][j]);
        *(float4*)(op + j * 8) = make_float4(p0.x, p0.y, p1.x, p1.y);
    }
}

__device__ __forceinline__ float gelu_exact(float v) {
    return 0.5f * v * (1.0f + erff(v * 0.70710678118654752f));
}

// ---------------- K5b: GEMM2 pso[fs][e][d][m] = gelu(sum pu) . W2 ----------------
// grid (dc=2, e=8, fs=32) = 512 blocks; same cp.async double-buffer staging.
__global__ __launch_bounds__(256) void k5b_gemm2(const float* __restrict__ W2) {
    __shared__ float us[128 * 8];
    __shared__ __align__(16) float wt[2][8 * 512];   // 32 KB
    int tid = threadIdx.x;
    int dc = blockIdx.x, e = blockIdx.y, fs = blockIdx.z;
    {   // stage u = gelu(sum of 8 k-split partials)
        int f = fs * 128 + (tid >> 1);
        int mb = (tid & 1) * 4;
        const float* pp = g_pu + ((size_t)e * DF + f) * 8 + mb;
        float4 s = *(const float4*)pp;
#pragma unroll
        for (int kq = 1; kq < KSPLIT; kq++) {
            float4 v = *(const float4*)(pp + (size_t)kq * NE * DF * 8);
            s.x += v.x; s.y += v.y; s.z += v.z; s.w += v.w;
        }
        float4 g;
        g.x = gelu_exact(s.x); g.y = gelu_exact(s.y);
        g.z = gelu_exact(s.z); g.w = gelu_exact(s.w);
        *(float4*)(us + tid * 4) = g;
    }
    int mh = tid >> 7;
    int dsl = tid & 127;
    const float* wbase = W2 + ((size_t)e * DF + fs * 128) * DM + dc * 512;

#pragma unroll
    for (int i = 0; i < 4; i++) {
        int chunk = i * 256 + tid;
        int row = chunk >> 7, col = chunk & 127;
        cp16(&wt[0][row * 512 + col * 4], wbase + (size_t)row * DM + col * 4);
    }
    CP_COMMIT();

    u64t accp[2][4];
#pragma unroll
    for (int i = 0; i < 2; i++)
#pragma unroll
        for (int j = 0; j < 4; j++) accp[i][j] = 0ull;

#pragma unroll 1
    for (int c = 0; c < 16; c++) {
        if (c + 1 < 16) {
            const float* src = wbase + (size_t)(c + 1) * 8 * DM;
            float* dst = wt[(c + 1) & 1];
#pragma unroll
            for (int i = 0; i < 4; i++) {
                int chunk = i * 256 + tid;
                int row = chunk >> 7, col = chunk & 127;
                cp16(&dst[row * 512 + col * 4], src + (size_t)row * DM + col * 4);
            }
        }
        CP_COMMIT();
        CP_WAIT1();
        __syncthreads();
        const float* wts = wt[c & 1];
#pragma unroll
        for (int r = 0; r < 8; r++) {
            float4 w = *(const float4*)(wts + r * 512 + dsl * 4);
            CONSUME1P(accp, us, c * 8 + r, mh, w)
        }
        __syncthreads();
    }
    int d0 = dc * 512 + dsl * 4;
    float* op = g_pso + ((size_t)(fs * NE + e) * DM + d0) * 8 + mh * 4;
#pragma unroll
    for (int j = 0; j < 4; j++) {
        float2 p0 = upk(accp[0][j]), p1 = upk(accp[1][j]);
        *(float4*)(op + j * 8) = make_float4(p0.x, p0.y, p1.x, p1.y);
    }
}

// ---------------- K5c: reduce 32 f-split partials -> slot_out[b][n][d] ----------------
__global__ __launch_bounds__(128) void k5c_reduce() {
    int idx = blockIdx.x * 128 + threadIdx.x;  // 0..16383
    int e = idx >> 11;
    int rest = idx & 2047;
    int d = rest >> 1, mh = rest & 1;
    const float* pp = g_pso + ((size_t)e * DM + d) * 8 + mh * 4;
    float4 a = *(const float4*)pp;
#pragma unroll 8
    for (int fs = 1; fs < FSPLIT; fs++) {
        float4 v = *(const float4*)(pp + (size_t)fs * NE * DM * 8);
        a.x += v.x; a.y += v.y; a.z += v.z; a.w += v.w;
    }
    int m0 = mh * 4;
    float vals[4] = {a.x, a.y, a.z, a.w};
#pragma unroll
    for (int j = 0; j < 4; j++) {
        int m = m0 + j;
        int b = m >> 1, sl = m & 1;
        g_so[(size_t)(b * 16 + e * 2 + sl) * DM + d] = vals[j];
    }
}

// ---------------- K6: combine = softmax_n(logits) @ slot_out ----------------
__global__ __launch_bounds__(256) void k6_combine(float* __restrict__ out) {
    __shared__ float cs[64 * 16];
    int tc = blockIdx.x, b = blockIdx.y;
    int tid = threadIdx.x;
    int t0 = tc * 64;
    if (tid < 64) {
        const float* lp = g_logits + (size_t)(b * TT + t0 + tid) * NSLOT;
        float l[16];
#pragma unroll
        for (int n = 0; n < 16; n++) l[n] = lp[n];
        float m = l[0];
#pragma unroll
        for (int n = 1; n < 16; n++) m = fmaxf(m, l[n]);
        float sum = 0.f;
#pragma unroll
        for (int n = 0; n < 16; n++) { l[n] = expf(l[n] - m); sum += l[n]; }
        float inv = 1.0f / sum;
#pragma unroll
        for (int n = 0; n < 16; n++) cs[tid * 16 + n] = l[n] * inv;
    }
    __syncthreads();
    u64t svp[16][2];
    const float* sp = g_so + (size_t)b * 16 * DM + tid * 4;
#pragma unroll
    for (int n = 0; n < 16; n++) {
        float4 v = *(const float4*)(sp + (size_t)n * DM);
        svp[n][0] = pk2(v.x, v.y);
        svp[n][1] = pk2(v.z, v.w);
    }
    float* op = out + (size_t)(b * TT + t0) * DM + tid * 4;
    for (int t = 0; t < 64; t++) {
        u64t a0 = 0ull, a1 = 0ull;
#pragma unroll
        for (int n = 0; n < 16; n++) {
            u64t cd = dup2f(cs[t * 16 + n]);
            fma2(a0, svp[n][0], cd);
            fma2(a1, svp[n][1], cd);
        }
        float2 p0 = upk(a0), p1 = upk(a1);
        *(float4*)(op + (size_t)t * DM) = make_float4(p0.x, p0.y, p1.x, p1.y);
    }
}

// ---------------- launch ----------------
extern "C" void kernel_launch(void* const* d_in, const int* in_sizes, int n_in,
                              void* d_out, int out_size) {
    const float* x     = (const float*)d_in[0];
    const float* se    = (const float*)d_in[1];
    const float* W1    = (const float*)d_in[2];
    const float* W2    = (const float*)d_in[3];
    const float* gamma = (const float*)d_in[4];
    const float* beta  = (const float*)d_in[5];
    float* out = (float*)d_out;

    { dim3 g(NCHUNK, BB);        k13_fused<<<g, 256>>>(x, se); }
    { dim3 g(64, 4);             k4a_reduce<<<g, 256>>>(); }
    k4b_stats<<<1, 64>>>();
    { dim3 g(8, NE, KSPLIT);     k5_gemm1<<<g, 256>>>(W1, gamma, beta); }
    { dim3 g(2, NE, FSPLIT);     k5b_gemm2<<<g, 256>>>(W2); }
    k5c_reduce<<<128, 128>>>();
    { dim3 g(64, BB);            k6_combine<<<g, 256>>>(out); }
}